// round 1
// baseline (speedup 1.0000x reference)
#include <cuda_runtime.h>
#include <math.h>

// Problem constants
#define B_   2
#define S_   2048
#define C_   2048
#define H_   16
#define DH_  128
#define RS_  (3*C_)      // qkv row stride = 6144

// Scratch (device globals: allocation-free rule)
__device__ float g_qkv[(size_t)B_*S_*3*C_];   // 100.7 MB: [4096][6144], cols: [K | Q | V]
__device__ float g_attn[(size_t)B_*S_*C_];    // 33.5 MB
__device__ float g_cos[S_*64];
__device__ float g_sin[S_*64];

// ---------------------------------------------------------------------------
// RoPE table: accurate sin/cos (double range reduction) of fp32 angles
// ---------------------------------------------------------------------------
__global__ void rope_table_kernel() {
    int idx = blockIdx.x * blockDim.x + threadIdx.x;
    if (idx >= S_*64) return;
    int s = idx >> 6, d = idx & 63;
    float invf = (float)pow(10000.0, -(double)d / 64.0);
    float ang  = (float)s * invf;               // match reference fp32 angle
    double a = (double)ang;
    g_cos[idx] = (float)cos(a);
    g_sin[idx] = (float)sin(a);
}

// ---------------------------------------------------------------------------
// RoPE apply (in-place on K and Q sections of g_qkv). Q also pre-scaled by
// Dh^-0.5 so attention skips the score scale.
// ---------------------------------------------------------------------------
__global__ void rope_apply_kernel() {
    int idx = blockIdx.x * blockDim.x + threadIdx.x;
    const int total = 2 * B_ * S_ * H_ * 64;
    if (idx >= total) return;
    int d = idx & 63;  int t = idx >> 6;
    int h = t & (H_-1);  t >>= 4;
    int s = t & (S_-1);  t >>= 11;
    int b = t & 1;  int sec = t >> 1;           // 0 = K cols, 1 = Q cols
    size_t base = (size_t)(b*S_ + s) * RS_ + sec*C_ + h*DH_ + d;
    float c  = g_cos[s*64 + d];
    float sn = g_sin[s*64 + d];
    float t1 = g_qkv[base], t2 = g_qkv[base + 64];
    float scale = sec ? 0.08838834764831845f : 1.0f;   // Dh^-0.5 on Q only
    g_qkv[base]      = (t1*c - t2*sn) * scale;
    g_qkv[base + 64] = (t2*c + t1*sn) * scale;
}

// ---------------------------------------------------------------------------
// SGEMM: C[M,N] = A[M,K] @ B[K,N], row-major, 128x128x16 tile, 8x8 microtile
// ---------------------------------------------------------------------------
__global__ void __launch_bounds__(256) sgemm128(const float* __restrict__ A,
                                                const float* __restrict__ B,
                                                float* __restrict__ C,
                                                int M, int N, int K) {
    __shared__ float As[16][132];   // transposed A tile, padded
    __shared__ float Bs[16][128];

    const int tid = threadIdx.x;
    const int bm = blockIdx.y * 128, bn = blockIdx.x * 128;
    const int tx = tid & 15, ty = tid >> 4;

    const int arow0 = tid >> 2, ac4 = (tid & 3) * 4;     // A tile f4 coords
    const int brow0 = tid >> 5, bc4 = (tid & 31) * 4;    // B tile f4 coords

    float acc[8][8];
    #pragma unroll
    for (int i = 0; i < 8; i++)
        #pragma unroll
        for (int j = 0; j < 8; j++) acc[i][j] = 0.f;

    for (int k0 = 0; k0 < K; k0 += 16) {
        #pragma unroll
        for (int t = 0; t < 2; t++) {
            int r = arow0 + t * 64;
            float4 av = *(const float4*)(A + (size_t)(bm + r) * K + k0 + ac4);
            As[ac4+0][r] = av.x; As[ac4+1][r] = av.y;
            As[ac4+2][r] = av.z; As[ac4+3][r] = av.w;
            int rb = brow0 + t * 8;
            *(float4*)(&Bs[rb][bc4]) =
                *(const float4*)(B + (size_t)(k0 + rb) * N + bn + bc4);
        }
        __syncthreads();
        #pragma unroll
        for (int k = 0; k < 16; k++) {
            float ar[8], br[8];
            *(float4*)(ar)     = *(float4*)(&As[k][ty*4]);
            *(float4*)(ar + 4) = *(float4*)(&As[k][ty*4 + 64]);
            *(float4*)(br)     = *(float4*)(&Bs[k][tx*4]);
            *(float4*)(br + 4) = *(float4*)(&Bs[k][tx*4 + 64]);
            #pragma unroll
            for (int i = 0; i < 8; i++)
                #pragma unroll
                for (int j = 0; j < 8; j++)
                    acc[i][j] += ar[i] * br[j];
        }
        __syncthreads();
    }

    #pragma unroll
    for (int i = 0; i < 8; i++) {
        int r = bm + ty*4 + (i < 4 ? i : 60 + i);
        float4 v0 = make_float4(acc[i][0], acc[i][1], acc[i][2], acc[i][3]);
        float4 v1 = make_float4(acc[i][4], acc[i][5], acc[i][6], acc[i][7]);
        *(float4*)(C + (size_t)r * N + bn + tx*4)      = v0;
        *(float4*)(C + (size_t)r * N + bn + tx*4 + 64) = v1;
    }
}

// ---------------------------------------------------------------------------
// Flash attention (causal, online softmax). Br=Bc=64, 256 threads.
// Reads K/Q/V from g_qkv (Q pre-scaled), writes g_attn[b*S+s][h*DH+d].
// ---------------------------------------------------------------------------
#define BR  64
#define BC  64
#define SQK 129   // Q/K smem row stride (scalar access, <=2-way conflicts)
#define SVV 132   // V smem row stride (float4 aligned)
#define SSS 65    // score smem row stride

#define ATTN_SMEM_FLOATS (BR*SQK + BC*SQK + BC*SVV + BR*SSS + 3*BR)

__global__ void __launch_bounds__(256) attn_kernel() {
    extern __shared__ float sm[];
    float* Qs   = sm;                    // 64*129
    float* Ks   = Qs + BR*SQK;           // 64*129
    float* Vs   = Ks + BC*SQK;           // 64*132  (float4-aligned base)
    float* Ss   = Vs + BC*SVV;           // 64*65
    float* mrow = Ss + BR*SSS;
    float* lrow = mrow + BR;
    float* arow = lrow + BR;

    const int tid = threadIdx.x;
    const int qb = blockIdx.x, h = blockIdx.y, b = blockIdx.z;
    const int q0 = qb * BR;

    // Load Q tile (rope'd + scaled already): section Q at col offset C_
    for (int f = tid; f < BR*32; f += 256) {
        int r = f >> 5, c4 = (f & 31) * 4;
        float4 qv = *(const float4*)(g_qkv + (size_t)(b*S_ + q0 + r) * RS_ + C_ + h*DH_ + c4);
        Qs[r*SQK + c4+0] = qv.x; Qs[r*SQK + c4+1] = qv.y;
        Qs[r*SQK + c4+2] = qv.z; Qs[r*SQK + c4+3] = qv.w;
    }
    if (tid < BR) { mrow[tid] = -1e30f; lrow[tid] = 0.f; }

    const int rr = (tid & 15) * 4;       // 4 query rows owned by this thread
    const int cc = (tid >> 4) * 4;       // 4 key cols (score phase)
    const int ds = (tid >> 4) * 8;       // 8 head dims (AV phase)

    float o[4][8];
    #pragma unroll
    for (int i = 0; i < 4; i++)
        #pragma unroll
        for (int k = 0; k < 8; k++) o[i][k] = 0.f;

    for (int kb = 0; kb <= qb; kb++) {
        __syncthreads();   // protect Ks/Vs/Ss from previous iteration readers
        for (int f = tid; f < BC*32; f += 256) {
            int r = f >> 5, c4 = (f & 31) * 4;
            size_t grow = (size_t)(b*S_ + kb*BC + r);
            float4 kv = *(const float4*)(g_qkv + grow * RS_ + h*DH_ + c4);          // K section
            Ks[r*SQK + c4+0] = kv.x; Ks[r*SQK + c4+1] = kv.y;
            Ks[r*SQK + c4+2] = kv.z; Ks[r*SQK + c4+3] = kv.w;
            *(float4*)(Vs + r*SVV + c4) =
                *(const float4*)(g_qkv + grow * RS_ + 2*C_ + h*DH_ + c4);           // V section
        }
        __syncthreads();

        // QK^T 4x4 microtile
        float s4[4][4];
        #pragma unroll
        for (int i = 0; i < 4; i++)
            #pragma unroll
            for (int j = 0; j < 4; j++) s4[i][j] = 0.f;

        #pragma unroll 4
        for (int d = 0; d < DH_; d++) {
            float qreg[4], kreg[4];
            #pragma unroll
            for (int i = 0; i < 4; i++) qreg[i] = Qs[(rr+i)*SQK + d];
            #pragma unroll
            for (int j = 0; j < 4; j++) kreg[j] = Ks[(cc+j)*SQK + d];
            #pragma unroll
            for (int i = 0; i < 4; i++)
                #pragma unroll
                for (int j = 0; j < 4; j++)
                    s4[i][j] += qreg[i] * kreg[j];
        }

        // causal mask + stage scores
        #pragma unroll
        for (int i = 0; i < 4; i++) {
            int qq = q0 + rr + i;
            #pragma unroll
            for (int j = 0; j < 4; j++) {
                int kk = kb*BC + cc + j;
                Ss[(rr+i)*SSS + cc + j] = (kk > qq) ? -1e30f : s4[i][j];
            }
        }
        __syncthreads();

        // online softmax row pass (one thread per row)
        if (tid < BR) {
            float mold = mrow[tid], mnew = mold;
            #pragma unroll 8
            for (int j = 0; j < BC; j++) mnew = fmaxf(mnew, Ss[tid*SSS + j]);
            float alpha = __expf(mold - mnew);
            float sum = 0.f;
            #pragma unroll 8
            for (int j = 0; j < BC; j++) {
                float p = __expf(Ss[tid*SSS + j] - mnew);
                Ss[tid*SSS + j] = p;
                sum += p;
            }
            lrow[tid] = lrow[tid] * alpha + sum;
            mrow[tid] = mnew;
            arow[tid] = alpha;
        }
        __syncthreads();

        // rescale accumulators then O += P @ V  (4 rows x 8 dims)
        {
            float av[4];
            #pragma unroll
            for (int i = 0; i < 4; i++) av[i] = arow[rr + i];
            #pragma unroll
            for (int i = 0; i < 4; i++)
                #pragma unroll
                for (int k = 0; k < 8; k++) o[i][k] *= av[i];
        }
        #pragma unroll 2
        for (int j = 0; j < BC; j++) {
            float4 v0 = *(float4*)(Vs + j*SVV + ds);
            float4 v1 = *(float4*)(Vs + j*SVV + ds + 4);
            #pragma unroll
            for (int i = 0; i < 4; i++) {
                float p = Ss[(rr+i)*SSS + j];
                o[i][0] += p * v0.x; o[i][1] += p * v0.y;
                o[i][2] += p * v0.z; o[i][3] += p * v0.w;
                o[i][4] += p * v1.x; o[i][5] += p * v1.y;
                o[i][6] += p * v1.z; o[i][7] += p * v1.w;
            }
        }
    }

    // normalize + write
    #pragma unroll
    for (int i = 0; i < 4; i++) {
        float nn = 1.f / lrow[rr + i];
        size_t grow = (size_t)(b*S_ + q0 + rr + i);
        float4 w0 = make_float4(o[i][0]*nn, o[i][1]*nn, o[i][2]*nn, o[i][3]*nn);
        float4 w1 = make_float4(o[i][4]*nn, o[i][5]*nn, o[i][6]*nn, o[i][7]*nn);
        *(float4*)(g_attn + grow*C_ + h*DH_ + ds)     = w0;
        *(float4*)(g_attn + grow*C_ + h*DH_ + ds + 4) = w1;
    }
}

// ---------------------------------------------------------------------------
extern "C" void kernel_launch(void* const* d_in, const int* in_sizes, int n_in,
                              void* d_out, int out_size) {
    const float* x     = (const float*)d_in[0];
    const float* Wqkv  = (const float*)d_in[1];
    const float* Wproj = (const float*)d_in[2];
    float* out = (float*)d_out;

    float *qkv_p, *attn_p;
    cudaGetSymbolAddress((void**)&qkv_p,  g_qkv);
    cudaGetSymbolAddress((void**)&attn_p, g_attn);

    // 1) RoPE sin/cos table
    rope_table_kernel<<<(S_*64 + 255)/256, 256>>>();

    // 2) qkv = x @ Wqkv   [4096 x 6144]
    sgemm128<<<dim3((3*C_)/128, (B_*S_)/128), 256>>>(x, Wqkv, qkv_p,
                                                     B_*S_, 3*C_, C_);

    // 3) RoPE on K and Q sections (Q pre-scaled by Dh^-0.5)
    rope_apply_kernel<<<(2*B_*S_*H_*64 + 255)/256, 256>>>();

    // 4) causal flash attention -> g_attn
    int smem_bytes = ATTN_SMEM_FLOATS * (int)sizeof(float);
    cudaFuncSetAttribute(attn_kernel,
                         cudaFuncAttributeMaxDynamicSharedMemorySize, smem_bytes);
    attn_kernel<<<dim3(S_/BR, H_, B_), 256, smem_bytes>>>();

    // 5) out = attn @ Wproj   [4096 x 2048]
    sgemm128<<<dim3(C_/128, (B_*S_)/128), 256>>>(attn_p, Wproj, out,
                                                 B_*S_, C_, C_);
}

// round 3
// speedup vs baseline: 1.4429x; 1.4429x over previous
#include <cuda_runtime.h>
#include <cuda_bf16.h>
#include <math.h>
#include <stdint.h>

// Problem constants
#define B_   2
#define S_   2048
#define C_   2048
#define H_   16
#define DH_  128
#define RS_  (3*C_)      // qkv row stride = 6144
#define K3_  (3*C_)      // split-bf16 concatenated K = 6144

// Scratch (device globals: allocation-free rule)
__device__ float g_qkv[(size_t)B_*S_*3*C_];        // 100.7 MB
__device__ float g_attn[(size_t)B_*S_*C_];         // 33.5 MB
__device__ __nv_bfloat16 g_A2[(size_t)B_*S_*K3_];  // 50.3 MB  [4096][6144]
__device__ __nv_bfloat16 g_B2[(size_t)K3_*K3_];    // 75.5 MB  [N<=6144][6144]
__device__ float g_cos[S_*64];
__device__ float g_sin[S_*64];

__device__ __forceinline__ uint32_t smem_u32(const void* p) {
    uint32_t a;
    asm("{ .reg .u64 t; cvta.to.shared.u64 t, %1; cvt.u32.u64 %0, t; }" : "=r"(a) : "l"(p));
    return a;
}

// ---------------------------------------------------------------------------
// RoPE table: accurate sin/cos of fp32 angles
// ---------------------------------------------------------------------------
__global__ void rope_table_kernel() {
    int idx = blockIdx.x * blockDim.x + threadIdx.x;
    if (idx >= S_*64) return;
    int s = idx >> 6, d = idx & 63;
    float invf = (float)pow(10000.0, -(double)d / 64.0);
    float ang  = (float)s * invf;
    double a = (double)ang;
    g_cos[idx] = (float)cos(a);
    g_sin[idx] = (float)sin(a);
}

// ---------------------------------------------------------------------------
// RoPE apply on K/Q of g_qkv (Q pre-scaled by Dh^-0.5)
// ---------------------------------------------------------------------------
__global__ void rope_apply_kernel() {
    int idx = blockIdx.x * blockDim.x + threadIdx.x;
    const int total = 2 * B_ * S_ * H_ * 64;
    if (idx >= total) return;
    int d = idx & 63;  int t = idx >> 6;
    int h = t & (H_-1);  t >>= 4;
    int s = t & (S_-1);  t >>= 11;
    int b = t & 1;  int sec = t >> 1;
    size_t base = (size_t)(b*S_ + s) * RS_ + sec*C_ + h*DH_ + d;
    float c  = g_cos[s*64 + d];
    float sn = g_sin[s*64 + d];
    float t1 = g_qkv[base], t2 = g_qkv[base + 64];
    float scale = sec ? 0.08838834764831845f : 1.0f;
    g_qkv[base]      = (t1*c - t2*sn) * scale;
    g_qkv[base + 64] = (t2*c + t1*sn) * scale;
}

// ---------------------------------------------------------------------------
// Split-bf16 conversions.
// A2[m] = [hi(A) | hi(A) | lo(A)]
// ---------------------------------------------------------------------------
__global__ void conv_A_kernel(const float* __restrict__ A, int K) {
    int idx = blockIdx.x * blockDim.x + threadIdx.x;
    int k = idx & (K-1);
    int m = idx >> 11;            // K == 2048 always here
    float v = A[idx];
    __nv_bfloat16 hi = __float2bfloat16(v);
    __nv_bfloat16 lo = __float2bfloat16(v - __bfloat162float(hi));
    size_t base = (size_t)m * K3_;
    g_A2[base + k]         = hi;
    g_A2[base + K + k]     = hi;
    g_A2[base + 2*K + k]   = lo;
}

// B2t[n] = [hi(B^T) | lo(B^T) | hi(B^T)], B given row-major [K][N]
__global__ void conv_B_kernel(const float* __restrict__ W, int K, int N) {
    __shared__ float tile[32][33];
    int n0 = blockIdx.x * 32, k0 = blockIdx.y * 32;
    int tx = threadIdx.x, ty = threadIdx.y;     // (32, 8)
    #pragma unroll
    for (int j = 0; j < 4; j++)
        tile[ty + 8*j][tx] = W[(size_t)(k0 + ty + 8*j) * N + n0 + tx];
    __syncthreads();
    #pragma unroll
    for (int j = 0; j < 4; j++) {
        int n = n0 + ty + 8*j;
        int k = k0 + tx;
        float v = tile[tx][ty + 8*j];
        __nv_bfloat16 hi = __float2bfloat16(v);
        __nv_bfloat16 lo = __float2bfloat16(v - __bfloat162float(hi));
        size_t base = (size_t)n * K3_;
        g_B2[base + k]       = hi;
        g_B2[base + K + k]   = lo;
        g_B2[base + 2*K + k] = hi;
    }
}

// ---------------------------------------------------------------------------
// mma.sync bf16 GEMM: C[M,N] = A2[M,K3] @ B2t[N,K3]^T, fp32 accum.
// BM=BN=128, BK=32, 8 warps (64x32 each), cp.async double buffer.
// ---------------------------------------------------------------------------
#define GBM 128
#define GBN 128
#define GBK 32
#define LDT 40                    // padded smem row stride (bf16): 80 bytes
#define TILE_ELEMS (128*LDT)      // per operand per stage

__device__ __forceinline__ void cp16(uint32_t dst, const void* src) {
    asm volatile("cp.async.cg.shared.global [%0], [%1], 16;" :: "r"(dst), "l"(src));
}
__device__ __forceinline__ void ldm4(uint32_t& r0, uint32_t& r1, uint32_t& r2,
                                     uint32_t& r3, uint32_t addr) {
    asm volatile("ldmatrix.sync.aligned.m8n8.x4.shared.b16 {%0,%1,%2,%3}, [%4];"
        : "=r"(r0), "=r"(r1), "=r"(r2), "=r"(r3) : "r"(addr));
}
__device__ __forceinline__ void mma_bf16(float* c, uint32_t a0, uint32_t a1,
                                         uint32_t a2, uint32_t a3,
                                         uint32_t b0, uint32_t b1) {
    asm volatile("mma.sync.aligned.m16n8k16.row.col.f32.bf16.bf16.f32 "
        "{%0,%1,%2,%3}, {%4,%5,%6,%7}, {%8,%9}, {%0,%1,%2,%3};"
        : "+f"(c[0]), "+f"(c[1]), "+f"(c[2]), "+f"(c[3])
        : "r"(a0), "r"(a1), "r"(a2), "r"(a3), "r"(b0), "r"(b1));
}

__global__ void __launch_bounds__(256) gemm_bf16_split(
    const __nv_bfloat16* __restrict__ A, const __nv_bfloat16* __restrict__ Bt,
    float* __restrict__ C, int M, int N)
{
    __shared__ __nv_bfloat16 As[2][TILE_ELEMS];
    __shared__ __nv_bfloat16 Bs[2][TILE_ELEMS];

    const int tid  = threadIdx.x;
    const int lane = tid & 31, wid = tid >> 5;
    const int wm = wid >> 2, wn = wid & 3;          // warp grid 2 x 4
    const int bm = blockIdx.y * GBM, bn = blockIdx.x * GBN;

    const uint32_t aBase = smem_u32(As);
    const uint32_t bBase = smem_u32(Bs);

    // cp.async coords: 512 16B-chunks per operand per stage, 2 per thread
    const int r0g = tid >> 2, c0g = (tid & 3) * 8;           // chunk set 0
    const int r1g = (tid + 256) >> 2;                        // chunk set 1 (same c)

    // ldmatrix lane offsets (bytes within a stage)
    const uint32_t aRowSel = (lane & 15), aColSel = (lane >> 4) * 8;
    const uint32_t bRowSel = ((lane >> 4) * 8) + (lane & 7);
    const uint32_t bColSel = ((lane >> 3) & 1) * 8;

    float acc[4][4][4];
    #pragma unroll
    for (int i = 0; i < 4; i++)
        #pragma unroll
        for (int j = 0; j < 4; j++)
            #pragma unroll
            for (int r = 0; r < 4; r++) acc[i][j][r] = 0.f;

    const int NT = K3_ / GBK;   // 192

    // prologue: load stage 0
    {
        const int k0 = 0;
        cp16(aBase + (r0g*LDT + c0g)*2, A + (size_t)(bm + r0g)*K3_ + k0 + c0g);
        cp16(aBase + (r1g*LDT + c0g)*2, A + (size_t)(bm + r1g)*K3_ + k0 + c0g);
        cp16(bBase + (r0g*LDT + c0g)*2, Bt + (size_t)(bn + r0g)*K3_ + k0 + c0g);
        cp16(bBase + (r1g*LDT + c0g)*2, Bt + (size_t)(bn + r1g)*K3_ + k0 + c0g);
        asm volatile("cp.async.commit_group;");
    }

    for (int kt = 0; kt < NT; kt++) {
        const int s = kt & 1;
        if (kt + 1 < NT) {
            const int ns = (kt + 1) & 1;
            const int k0 = (kt + 1) * GBK;
            const uint32_t aOff = aBase + ns * TILE_ELEMS * 2;
            const uint32_t bOff = bBase + ns * TILE_ELEMS * 2;
            cp16(aOff + (r0g*LDT + c0g)*2, A + (size_t)(bm + r0g)*K3_ + k0 + c0g);
            cp16(aOff + (r1g*LDT + c0g)*2, A + (size_t)(bm + r1g)*K3_ + k0 + c0g);
            cp16(bOff + (r0g*LDT + c0g)*2, Bt + (size_t)(bn + r0g)*K3_ + k0 + c0g);
            cp16(bOff + (r1g*LDT + c0g)*2, Bt + (size_t)(bn + r1g)*K3_ + k0 + c0g);
            asm volatile("cp.async.commit_group;");
            asm volatile("cp.async.wait_group 1;");
        } else {
            asm volatile("cp.async.wait_group 0;");
        }
        __syncthreads();

        const uint32_t aS = aBase + s * TILE_ELEMS * 2;
        const uint32_t bS = bBase + s * TILE_ELEMS * 2;

        #pragma unroll
        for (int kc = 0; kc < 2; kc++) {
            // B frags: 2 x ldmatrix.x4 covers 4 n8-tiles
            uint32_t bf[4][2];
            #pragma unroll
            for (int np = 0; np < 2; np++) {
                uint32_t addr = bS + ((wn*32 + np*16 + bRowSel) * LDT
                                      + kc*16 + bColSel) * 2;
                uint32_t r0, r1, r2, r3;
                ldm4(r0, r1, r2, r3, addr);
                bf[np*2+0][0] = r0; bf[np*2+0][1] = r1;
                bf[np*2+1][0] = r2; bf[np*2+1][1] = r3;
            }
            #pragma unroll
            for (int mt = 0; mt < 4; mt++) {
                uint32_t addr = aS + ((wm*64 + mt*16 + aRowSel) * LDT
                                      + kc*16 + aColSel) * 2;
                uint32_t a0, a1, a2, a3;
                ldm4(a0, a1, a2, a3, addr);
                #pragma unroll
                for (int nt = 0; nt < 4; nt++)
                    mma_bf16(acc[mt][nt], a0, a1, a2, a3, bf[nt][0], bf[nt][1]);
            }
        }
        __syncthreads();
    }

    // epilogue: direct global write (float2 per reg pair)
    #pragma unroll
    for (int mt = 0; mt < 4; mt++) {
        const int r0 = bm + wm*64 + mt*16 + (lane >> 2);
        #pragma unroll
        for (int nt = 0; nt < 4; nt++) {
            const int col = bn + wn*32 + nt*8 + (lane & 3)*2;
            *(float2*)(C + (size_t)r0 * N + col) =
                make_float2(acc[mt][nt][0], acc[mt][nt][1]);
            *(float2*)(C + (size_t)(r0 + 8) * N + col) =
                make_float2(acc[mt][nt][2], acc[mt][nt][3]);
        }
    }
}

// ---------------------------------------------------------------------------
// Flash attention (causal, online softmax). Unchanged from R1.
// ---------------------------------------------------------------------------
#define BR  64
#define BC  64
#define SQK 129
#define SVV 132
#define SSS 65

#define ATTN_SMEM_FLOATS (BR*SQK + BC*SQK + BC*SVV + BR*SSS + 3*BR)

__global__ void __launch_bounds__(256) attn_kernel() {
    extern __shared__ float sm[];
    float* Qs   = sm;
    float* Ks   = Qs + BR*SQK;
    float* Vs   = Ks + BC*SQK;
    float* Ss   = Vs + BC*SVV;
    float* mrow = Ss + BR*SSS;
    float* lrow = mrow + BR;
    float* arow = lrow + BR;

    const int tid = threadIdx.x;
    const int qb = blockIdx.x, h = blockIdx.y, b = blockIdx.z;
    const int q0 = qb * BR;

    for (int f = tid; f < BR*32; f += 256) {
        int r = f >> 5, c4 = (f & 31) * 4;
        float4 qv = *(const float4*)(g_qkv + (size_t)(b*S_ + q0 + r) * RS_ + C_ + h*DH_ + c4);
        Qs[r*SQK + c4+0] = qv.x; Qs[r*SQK + c4+1] = qv.y;
        Qs[r*SQK + c4+2] = qv.z; Qs[r*SQK + c4+3] = qv.w;
    }
    if (tid < BR) { mrow[tid] = -1e30f; lrow[tid] = 0.f; }

    const int rr = (tid & 15) * 4;
    const int cc = (tid >> 4) * 4;
    const int ds = (tid >> 4) * 8;

    float o[4][8];
    #pragma unroll
    for (int i = 0; i < 4; i++)
        #pragma unroll
        for (int k = 0; k < 8; k++) o[i][k] = 0.f;

    for (int kb = 0; kb <= qb; kb++) {
        __syncthreads();
        for (int f = tid; f < BC*32; f += 256) {
            int r = f >> 5, c4 = (f & 31) * 4;
            size_t grow = (size_t)(b*S_ + kb*BC + r);
            float4 kv = *(const float4*)(g_qkv + grow * RS_ + h*DH_ + c4);
            Ks[r*SQK + c4+0] = kv.x; Ks[r*SQK + c4+1] = kv.y;
            Ks[r*SQK + c4+2] = kv.z; Ks[r*SQK + c4+3] = kv.w;
            *(float4*)(Vs + r*SVV + c4) =
                *(const float4*)(g_qkv + grow * RS_ + 2*C_ + h*DH_ + c4);
        }
        __syncthreads();

        float s4[4][4];
        #pragma unroll
        for (int i = 0; i < 4; i++)
            #pragma unroll
            for (int j = 0; j < 4; j++) s4[i][j] = 0.f;

        #pragma unroll 4
        for (int d = 0; d < DH_; d++) {
            float qreg[4], kreg[4];
            #pragma unroll
            for (int i = 0; i < 4; i++) qreg[i] = Qs[(rr+i)*SQK + d];
            #pragma unroll
            for (int j = 0; j < 4; j++) kreg[j] = Ks[(cc+j)*SQK + d];
            #pragma unroll
            for (int i = 0; i < 4; i++)
                #pragma unroll
                for (int j = 0; j < 4; j++)
                    s4[i][j] += qreg[i] * kreg[j];
        }

        #pragma unroll
        for (int i = 0; i < 4; i++) {
            int qq = q0 + rr + i;
            #pragma unroll
            for (int j = 0; j < 4; j++) {
                int kk = kb*BC + cc + j;
                Ss[(rr+i)*SSS + cc + j] = (kk > qq) ? -1e30f : s4[i][j];
            }
        }
        __syncthreads();

        if (tid < BR) {
            float mold = mrow[tid], mnew = mold;
            #pragma unroll 8
            for (int j = 0; j < BC; j++) mnew = fmaxf(mnew, Ss[tid*SSS + j]);
            float alpha = __expf(mold - mnew);
            float sum = 0.f;
            #pragma unroll 8
            for (int j = 0; j < BC; j++) {
                float p = __expf(Ss[tid*SSS + j] - mnew);
                Ss[tid*SSS + j] = p;
                sum += p;
            }
            lrow[tid] = lrow[tid] * alpha + sum;
            mrow[tid] = mnew;
            arow[tid] = alpha;
        }
        __syncthreads();

        {
            float av[4];
            #pragma unroll
            for (int i = 0; i < 4; i++) av[i] = arow[rr + i];
            #pragma unroll
            for (int i = 0; i < 4; i++)
                #pragma unroll
                for (int k = 0; k < 8; k++) o[i][k] *= av[i];
        }
        #pragma unroll 2
        for (int j = 0; j < BC; j++) {
            float4 v0 = *(float4*)(Vs + j*SVV + ds);
            float4 v1 = *(float4*)(Vs + j*SVV + ds + 4);
            #pragma unroll
            for (int i = 0; i < 4; i++) {
                float p = Ss[(rr+i)*SSS + j];
                o[i][0] += p * v0.x; o[i][1] += p * v0.y;
                o[i][2] += p * v0.z; o[i][3] += p * v0.w;
                o[i][4] += p * v1.x; o[i][5] += p * v1.y;
                o[i][6] += p * v1.z; o[i][7] += p * v1.w;
            }
        }
    }

    #pragma unroll
    for (int i = 0; i < 4; i++) {
        float nn = 1.f / lrow[rr + i];
        size_t grow = (size_t)(b*S_ + q0 + rr + i);
        float4 w0 = make_float4(o[i][0]*nn, o[i][1]*nn, o[i][2]*nn, o[i][3]*nn);
        float4 w1 = make_float4(o[i][4]*nn, o[i][5]*nn, o[i][6]*nn, o[i][7]*nn);
        *(float4*)(g_attn + grow*C_ + h*DH_ + ds)     = w0;
        *(float4*)(g_attn + grow*C_ + h*DH_ + ds + 4) = w1;
    }
}

// ---------------------------------------------------------------------------
extern "C" void kernel_launch(void* const* d_in, const int* in_sizes, int n_in,
                              void* d_out, int out_size) {
    const float* x     = (const float*)d_in[0];
    const float* Wqkv  = (const float*)d_in[1];
    const float* Wproj = (const float*)d_in[2];
    float* out = (float*)d_out;

    float *qkv_p, *attn_p;
    __nv_bfloat16 *a2_p, *b2_p;
    cudaGetSymbolAddress((void**)&qkv_p,  g_qkv);
    cudaGetSymbolAddress((void**)&attn_p, g_attn);
    cudaGetSymbolAddress((void**)&a2_p,   g_A2);
    cudaGetSymbolAddress((void**)&b2_p,   g_B2);

    // 1) RoPE sin/cos table
    rope_table_kernel<<<(S_*64 + 255)/256, 256>>>();

    // 2) split-bf16 conversions for GEMM1
    conv_A_kernel<<<(B_*S_*C_)/256, 256>>>(x, C_);
    conv_B_kernel<<<dim3((3*C_)/32, C_/32), dim3(32, 8)>>>(Wqkv, C_, 3*C_);

    // 3) qkv = x @ Wqkv  (mma.sync bf16-split)
    gemm_bf16_split<<<dim3((3*C_)/GBN, (B_*S_)/GBM), 256>>>(
        a2_p, b2_p, qkv_p, B_*S_, 3*C_);

    // 4) RoPE on K/Q (Q pre-scaled by Dh^-0.5)
    rope_apply_kernel<<<(2*B_*S_*H_*64 + 255)/256, 256>>>();

    // 5) causal flash attention -> g_attn
    int smem_bytes = ATTN_SMEM_FLOATS * (int)sizeof(float);
    cudaFuncSetAttribute(attn_kernel,
                         cudaFuncAttributeMaxDynamicSharedMemorySize, smem_bytes);
    attn_kernel<<<dim3(S_/BR, H_, B_), 256, smem_bytes>>>();

    // 6) split-bf16 conversions for GEMM2
    conv_A_kernel<<<(B_*S_*C_)/256, 256>>>(attn_p, C_);
    conv_B_kernel<<<dim3(C_/32, C_/32), dim3(32, 8)>>>(Wproj, C_, C_);

    // 7) out = attn @ Wproj  (mma.sync bf16-split)
    gemm_bf16_split<<<dim3(C_/GBN, (B_*S_)/GBM), 256>>>(
        a2_p, b2_p, out, B_*S_, C_);
}

// round 4
// speedup vs baseline: 2.3282x; 1.6136x over previous
#include <cuda_runtime.h>
#include <cuda_bf16.h>
#include <math.h>
#include <stdint.h>

// Problem constants
#define B_   2
#define S_   2048
#define C_   2048
#define H_   16
#define DH_  128
#define RS_  (3*C_)
#define K3_  (3*C_)
#define QSCALE 0.08838834764831845f

// Scratch (device globals)
__device__ float g_qkv[(size_t)B_*S_*3*C_];
__device__ float g_attn[(size_t)B_*S_*C_];
__device__ __nv_bfloat16 g_A2[(size_t)B_*S_*K3_];
__device__ __nv_bfloat16 g_B2[(size_t)K3_*K3_];
__device__ __nv_bfloat16 g_Q2[(size_t)B_*H_*S_*256];
__device__ __nv_bfloat16 g_K2[(size_t)B_*H_*S_*256];
__device__ __nv_bfloat16 g_V2[(size_t)B_*H_*S_*256];
__device__ float g_cos[S_*64];
__device__ float g_sin[S_*64];

__device__ __forceinline__ uint32_t smem_u32(const void* p) {
    uint32_t a;
    asm("{ .reg .u64 t; cvta.to.shared.u64 t, %1; cvt.u32.u64 %0, t; }" : "=r"(a) : "l"(p));
    return a;
}
__device__ __forceinline__ void cp16(uint32_t dst, const void* src) {
    asm volatile("cp.async.cg.shared.global [%0], [%1], 16;" :: "r"(dst), "l"(src));
}
__device__ __forceinline__ void ldm4(uint32_t& r0, uint32_t& r1, uint32_t& r2,
                                     uint32_t& r3, uint32_t addr) {
    asm volatile("ldmatrix.sync.aligned.m8n8.x4.shared.b16 {%0,%1,%2,%3}, [%4];"
        : "=r"(r0), "=r"(r1), "=r"(r2), "=r"(r3) : "r"(addr));
}
__device__ __forceinline__ void ldm4t(uint32_t& r0, uint32_t& r1, uint32_t& r2,
                                      uint32_t& r3, uint32_t addr) {
    asm volatile("ldmatrix.sync.aligned.m8n8.x4.trans.shared.b16 {%0,%1,%2,%3}, [%4];"
        : "=r"(r0), "=r"(r1), "=r"(r2), "=r"(r3) : "r"(addr));
}
__device__ __forceinline__ void mma_bf16(float* c, uint32_t a0, uint32_t a1,
                                         uint32_t a2, uint32_t a3,
                                         uint32_t b0, uint32_t b1) {
    asm volatile("mma.sync.aligned.m16n8k16.row.col.f32.bf16.bf16.f32 "
        "{%0,%1,%2,%3}, {%4,%5,%6,%7}, {%8,%9}, {%0,%1,%2,%3};"
        : "+f"(c[0]), "+f"(c[1]), "+f"(c[2]), "+f"(c[3])
        : "r"(a0), "r"(a1), "r"(a2), "r"(a3), "r"(b0), "r"(b1));
}
__device__ __forceinline__ void split_pack(float x, float y, uint32_t& hi, uint32_t& lo) {
    __nv_bfloat16 hx = __float2bfloat16(x);
    __nv_bfloat16 hy = __float2bfloat16(y);
    __nv_bfloat16 lx = __float2bfloat16(x - __bfloat162float(hx));
    __nv_bfloat16 ly = __float2bfloat16(y - __bfloat162float(hy));
    hi = (uint32_t)*(uint16_t*)&hx | ((uint32_t)*(uint16_t*)&hy << 16);
    lo = (uint32_t)*(uint16_t*)&lx | ((uint32_t)*(uint16_t*)&ly << 16);
}

// ---------------------------------------------------------------------------
// RoPE table
// ---------------------------------------------------------------------------
__global__ void rope_table_kernel() {
    int idx = blockIdx.x * blockDim.x + threadIdx.x;
    if (idx >= S_*64) return;
    int s = idx >> 6, d = idx & 63;
    float invf = (float)pow(10000.0, -(double)d / 64.0);
    float ang  = (float)s * invf;
    double a = (double)ang;
    g_cos[idx] = (float)cos(a);
    g_sin[idx] = (float)sin(a);
}

// ---------------------------------------------------------------------------
// Prep for attention: RoPE + scale + split-bf16, per-head layout [hi128|lo128]
// ---------------------------------------------------------------------------
__device__ __forceinline__ void split_st(__nv_bfloat16* dst, int off, float v) {
    __nv_bfloat16 hi = __float2bfloat16(v);
    dst[off]       = hi;
    dst[off + 128] = __float2bfloat16(v - __bfloat162float(hi));
}

__global__ void prep_attn_kernel() {
    int idx = blockIdx.x * blockDim.x + threadIdx.x;   // B*S*H*64
    int d0 = idx & 63;
    int h  = (idx >> 6) & 15;
    int s  = (idx >> 10) & 2047;
    int b  = idx >> 21;
    size_t row = (size_t)(b*S_ + s) * RS_ + h*DH_;
    float c  = g_cos[s*64 + d0];
    float sn = g_sin[s*64 + d0];

    float k1 = g_qkv[row + d0],        k2 = g_qkv[row + d0 + 64];
    float q1 = g_qkv[row + C_ + d0],   q2 = g_qkv[row + C_ + d0 + 64];
    float v1 = g_qkv[row + 2*C_ + d0], v2 = g_qkv[row + 2*C_ + d0 + 64];

    float kr1 = k1*c - k2*sn, kr2 = k2*c + k1*sn;
    float qr1 = (q1*c - q2*sn) * QSCALE, qr2 = (q2*c + q1*sn) * QSCALE;

    size_t orow = ((size_t)(b*H_ + h) * S_ + s) * 256;
    split_st(g_Q2 + orow, d0, qr1);  split_st(g_Q2 + orow, d0 + 64, qr2);
    split_st(g_K2 + orow, d0, kr1);  split_st(g_K2 + orow, d0 + 64, kr2);
    split_st(g_V2 + orow, d0, v1);   split_st(g_V2 + orow, d0 + 64, v2);
}

// ---------------------------------------------------------------------------
// Split-bf16 conversions for the dense GEMMs (unchanged)
// ---------------------------------------------------------------------------
__global__ void conv_A_kernel(const float* __restrict__ A, int K) {
    int idx = blockIdx.x * blockDim.x + threadIdx.x;
    int k = idx & (K-1);
    int m = idx >> 11;
    float v = A[idx];
    __nv_bfloat16 hi = __float2bfloat16(v);
    __nv_bfloat16 lo = __float2bfloat16(v - __bfloat162float(hi));
    size_t base = (size_t)m * K3_;
    g_A2[base + k]         = hi;
    g_A2[base + K + k]     = hi;
    g_A2[base + 2*K + k]   = lo;
}

__global__ void conv_B_kernel(const float* __restrict__ W, int K, int N) {
    __shared__ float tile[32][33];
    int n0 = blockIdx.x * 32, k0 = blockIdx.y * 32;
    int tx = threadIdx.x, ty = threadIdx.y;
    #pragma unroll
    for (int j = 0; j < 4; j++)
        tile[ty + 8*j][tx] = W[(size_t)(k0 + ty + 8*j) * N + n0 + tx];
    __syncthreads();
    #pragma unroll
    for (int j = 0; j < 4; j++) {
        int n = n0 + ty + 8*j;
        int k = k0 + tx;
        float v = tile[tx][ty + 8*j];
        __nv_bfloat16 hi = __float2bfloat16(v);
        __nv_bfloat16 lo = __float2bfloat16(v - __bfloat162float(hi));
        size_t base = (size_t)n * K3_;
        g_B2[base + k]       = hi;
        g_B2[base + K + k]   = lo;
        g_B2[base + 2*K + k] = hi;
    }
}

// ---------------------------------------------------------------------------
// mma.sync bf16 GEMM (unchanged from R3)
// ---------------------------------------------------------------------------
#define GBM 128
#define GBN 128
#define GBK 32
#define LDT 40
#define TILE_ELEMS (128*LDT)

__global__ void __launch_bounds__(256) gemm_bf16_split(
    const __nv_bfloat16* __restrict__ A, const __nv_bfloat16* __restrict__ Bt,
    float* __restrict__ C, int M, int N)
{
    __shared__ __nv_bfloat16 As[2][TILE_ELEMS];
    __shared__ __nv_bfloat16 Bs[2][TILE_ELEMS];

    const int tid  = threadIdx.x;
    const int lane = tid & 31, wid = tid >> 5;
    const int wm = wid >> 2, wn = wid & 3;
    const int bm = blockIdx.y * GBM, bn = blockIdx.x * GBN;

    const uint32_t aBase = smem_u32(As);
    const uint32_t bBase = smem_u32(Bs);

    const int r0g = tid >> 2, c0g = (tid & 3) * 8;
    const int r1g = (tid + 256) >> 2;

    const uint32_t aRowSel = (lane & 15), aColSel = (lane >> 4) * 8;
    const uint32_t bRowSel = ((lane >> 4) * 8) + (lane & 7);
    const uint32_t bColSel = ((lane >> 3) & 1) * 8;

    float acc[4][4][4];
    #pragma unroll
    for (int i = 0; i < 4; i++)
        #pragma unroll
        for (int j = 0; j < 4; j++)
            #pragma unroll
            for (int r = 0; r < 4; r++) acc[i][j][r] = 0.f;

    const int NT = K3_ / GBK;

    {
        const int k0 = 0;
        cp16(aBase + (r0g*LDT + c0g)*2, A + (size_t)(bm + r0g)*K3_ + k0 + c0g);
        cp16(aBase + (r1g*LDT + c0g)*2, A + (size_t)(bm + r1g)*K3_ + k0 + c0g);
        cp16(bBase + (r0g*LDT + c0g)*2, Bt + (size_t)(bn + r0g)*K3_ + k0 + c0g);
        cp16(bBase + (r1g*LDT + c0g)*2, Bt + (size_t)(bn + r1g)*K3_ + k0 + c0g);
        asm volatile("cp.async.commit_group;");
    }

    for (int kt = 0; kt < NT; kt++) {
        const int s = kt & 1;
        if (kt + 1 < NT) {
            const int ns = (kt + 1) & 1;
            const int k0 = (kt + 1) * GBK;
            const uint32_t aOff = aBase + ns * TILE_ELEMS * 2;
            const uint32_t bOff = bBase + ns * TILE_ELEMS * 2;
            cp16(aOff + (r0g*LDT + c0g)*2, A + (size_t)(bm + r0g)*K3_ + k0 + c0g);
            cp16(aOff + (r1g*LDT + c0g)*2, A + (size_t)(bm + r1g)*K3_ + k0 + c0g);
            cp16(bOff + (r0g*LDT + c0g)*2, Bt + (size_t)(bn + r0g)*K3_ + k0 + c0g);
            cp16(bOff + (r1g*LDT + c0g)*2, Bt + (size_t)(bn + r1g)*K3_ + k0 + c0g);
            asm volatile("cp.async.commit_group;");
            asm volatile("cp.async.wait_group 1;");
        } else {
            asm volatile("cp.async.wait_group 0;");
        }
        __syncthreads();

        const uint32_t aS = aBase + s * TILE_ELEMS * 2;
        const uint32_t bS = bBase + s * TILE_ELEMS * 2;

        #pragma unroll
        for (int kc = 0; kc < 2; kc++) {
            uint32_t bf[4][2];
            #pragma unroll
            for (int np = 0; np < 2; np++) {
                uint32_t addr = bS + ((wn*32 + np*16 + bRowSel) * LDT
                                      + kc*16 + bColSel) * 2;
                uint32_t r0, r1, r2, r3;
                ldm4(r0, r1, r2, r3, addr);
                bf[np*2+0][0] = r0; bf[np*2+0][1] = r1;
                bf[np*2+1][0] = r2; bf[np*2+1][1] = r3;
            }
            #pragma unroll
            for (int mt = 0; mt < 4; mt++) {
                uint32_t addr = aS + ((wm*64 + mt*16 + aRowSel) * LDT
                                      + kc*16 + aColSel) * 2;
                uint32_t a0, a1, a2, a3;
                ldm4(a0, a1, a2, a3, addr);
                #pragma unroll
                for (int nt = 0; nt < 4; nt++)
                    mma_bf16(acc[mt][nt], a0, a1, a2, a3, bf[nt][0], bf[nt][1]);
            }
        }
        __syncthreads();
    }

    #pragma unroll
    for (int mt = 0; mt < 4; mt++) {
        const int r0 = bm + wm*64 + mt*16 + (lane >> 2);
        #pragma unroll
        for (int nt = 0; nt < 4; nt++) {
            const int col = bn + wn*32 + nt*8 + (lane & 3)*2;
            *(float2*)(C + (size_t)r0 * N + col) =
                make_float2(acc[mt][nt][0], acc[mt][nt][1]);
            *(float2*)(C + (size_t)(r0 + 8) * N + col) =
                make_float2(acc[mt][nt][2], acc[mt][nt][3]);
        }
    }
}

// ---------------------------------------------------------------------------
// Tensor-core flash attention (causal), split-bf16, 128 q-rows per CTA.
// ---------------------------------------------------------------------------
#define ABR 128
#define ABC 64
#define ALD 264
#define QS_ELEMS (ABR*ALD)
#define KV_ELEMS (ABC*ALD)
#define ATT_SMEM ((QS_ELEMS + 4*KV_ELEMS)*2)

__global__ void __launch_bounds__(256, 1) attn_mma_kernel() {
    extern __shared__ __nv_bfloat16 attsm[];
    __nv_bfloat16* Qs = attsm;
    __nv_bfloat16* Ks = attsm + QS_ELEMS;               // [2][KV_ELEMS]
    __nv_bfloat16* Vs = attsm + QS_ELEMS + 2*KV_ELEMS;  // [2][KV_ELEMS]

    const int tid = threadIdx.x, lane = tid & 31, wid = tid >> 5;
    const int qt = gridDim.x - 1 - blockIdx.x;     // heavy tiles first
    const int bh = blockIdx.y;
    const int q0 = qt * ABR;
    const size_t gbase = (size_t)bh * S_ * 256;

    const uint32_t qsB = smem_u32(Qs), ksB = smem_u32(Ks), vsB = smem_u32(Vs);

    // prologue: Q tile + K/V tile 0 in one cp.async group
    {
        const __nv_bfloat16* qsrc = g_Q2 + gbase + (size_t)q0 * 256;
        #pragma unroll
        for (int i = 0; i < 16; i++) {
            int ch = tid + i*256;
            int r = ch >> 5, c8 = (ch & 31) * 8;
            cp16(qsB + (r*ALD + c8)*2, qsrc + (size_t)r*256 + c8);
        }
        const __nv_bfloat16* ksrc = g_K2 + gbase;
        const __nv_bfloat16* vsrc = g_V2 + gbase;
        #pragma unroll
        for (int i = 0; i < 8; i++) {
            int ch = tid + i*256;
            int r = ch >> 5, c8 = (ch & 31) * 8;
            cp16(ksB + (r*ALD + c8)*2, ksrc + (size_t)r*256 + c8);
            cp16(vsB + (r*ALD + c8)*2, vsrc + (size_t)r*256 + c8);
        }
        asm volatile("cp.async.commit_group;");
    }

    const int lr = lane >> 2, lc = lane & 3;
    const int wq = wid * 16;

    float m0 = -1e30f, m1 = -1e30f, l0 = 0.f, l1 = 0.f;
    float o[16][4];
    #pragma unroll
    for (int i = 0; i < 16; i++)
        #pragma unroll
        for (int j = 0; j < 4; j++) o[i][j] = 0.f;

    const int nkb = 2*qt + 2;

    for (int kb = 0; kb < nkb; kb++) {
        const int s = kb & 1;
        if (kb + 1 < nkb) {
            const int ns = s ^ 1;
            const __nv_bfloat16* ksrc = g_K2 + gbase + (size_t)((kb+1)*ABC) * 256;
            const __nv_bfloat16* vsrc = g_V2 + gbase + (size_t)((kb+1)*ABC) * 256;
            uint32_t kd = ksB + ns*KV_ELEMS*2, vd = vsB + ns*KV_ELEMS*2;
            #pragma unroll
            for (int i = 0; i < 8; i++) {
                int ch = tid + i*256;
                int r = ch >> 5, c8 = (ch & 31) * 8;
                cp16(kd + (r*ALD + c8)*2, ksrc + (size_t)r*256 + c8);
                cp16(vd + (r*ALD + c8)*2, vsrc + (size_t)r*256 + c8);
            }
            asm volatile("cp.async.commit_group;");
            asm volatile("cp.async.wait_group 1;");
        } else {
            asm volatile("cp.async.wait_group 0;");
        }
        __syncthreads();

        const uint32_t ks0 = ksB + s*KV_ELEMS*2;
        const uint32_t vs0 = vsB + s*KV_ELEMS*2;

        // ---- S = Q'K'^T (3-term split) ----
        float sacc[8][4];
        #pragma unroll
        for (int i = 0; i < 8; i++)
            #pragma unroll
            for (int j = 0; j < 4; j++) sacc[i][j] = 0.f;

        #pragma unroll
        for (int kc = 0; kc < 8; kc++) {
            uint32_t qaddr = qsB + ((wq + (lane & 15))*ALD + kc*16 + (lane >> 4)*8)*2;
            uint32_t qh0,qh1,qh2,qh3, ql0,ql1,ql2,ql3;
            ldm4(qh0,qh1,qh2,qh3, qaddr);
            ldm4(ql0,ql1,ql2,ql3, qaddr + 128*2);
            #pragma unroll
            for (int ntp = 0; ntp < 4; ntp++) {
                uint32_t baddr = ks0 + ((ntp*16 + (lane>>4)*8 + (lane&7))*ALD
                                        + kc*16 + ((lane>>3)&1)*8)*2;
                uint32_t h0,h1,h2,h3, e0,e1,e2,e3;
                ldm4(h0,h1,h2,h3, baddr);
                ldm4(e0,e1,e2,e3, baddr + 128*2);
                mma_bf16(sacc[2*ntp],   qh0,qh1,qh2,qh3, h0,h1);
                mma_bf16(sacc[2*ntp],   qh0,qh1,qh2,qh3, e0,e1);
                mma_bf16(sacc[2*ntp],   ql0,ql1,ql2,ql3, h0,h1);
                mma_bf16(sacc[2*ntp+1], qh0,qh1,qh2,qh3, h2,h3);
                mma_bf16(sacc[2*ntp+1], qh0,qh1,qh2,qh3, e2,e3);
                mma_bf16(sacc[2*ntp+1], ql0,ql1,ql2,ql3, h2,h3);
            }
        }

        // ---- causal mask (only diagonal tiles) ----
        const int r0 = q0 + wq + lr, r1 = r0 + 8;
        if (kb >= 2*qt) {
            #pragma unroll
            for (int nt = 0; nt < 8; nt++) {
                int key = kb*ABC + nt*8 + 2*lc;
                if (key     > r0) sacc[nt][0] = -1e30f;
                if (key + 1 > r0) sacc[nt][1] = -1e30f;
                if (key     > r1) sacc[nt][2] = -1e30f;
                if (key + 1 > r1) sacc[nt][3] = -1e30f;
            }
        }

        // ---- online softmax ----
        float mx0 = m0, mx1 = m1;
        #pragma unroll
        for (int nt = 0; nt < 8; nt++) {
            mx0 = fmaxf(mx0, fmaxf(sacc[nt][0], sacc[nt][1]));
            mx1 = fmaxf(mx1, fmaxf(sacc[nt][2], sacc[nt][3]));
        }
        mx0 = fmaxf(mx0, __shfl_xor_sync(0xffffffffu, mx0, 1));
        mx0 = fmaxf(mx0, __shfl_xor_sync(0xffffffffu, mx0, 2));
        mx1 = fmaxf(mx1, __shfl_xor_sync(0xffffffffu, mx1, 1));
        mx1 = fmaxf(mx1, __shfl_xor_sync(0xffffffffu, mx1, 2));
        float a0 = __expf(m0 - mx0), a1 = __expf(m1 - mx1);
        m0 = mx0; m1 = mx1;

        float s0 = 0.f, s1 = 0.f;
        #pragma unroll
        for (int nt = 0; nt < 8; nt++) {
            sacc[nt][0] = __expf(sacc[nt][0] - m0); s0 += sacc[nt][0];
            sacc[nt][1] = __expf(sacc[nt][1] - m0); s0 += sacc[nt][1];
            sacc[nt][2] = __expf(sacc[nt][2] - m1); s1 += sacc[nt][2];
            sacc[nt][3] = __expf(sacc[nt][3] - m1); s1 += sacc[nt][3];
        }
        s0 += __shfl_xor_sync(0xffffffffu, s0, 1);
        s0 += __shfl_xor_sync(0xffffffffu, s0, 2);
        s1 += __shfl_xor_sync(0xffffffffu, s1, 1);
        s1 += __shfl_xor_sync(0xffffffffu, s1, 2);
        l0 = l0 * a0 + s0;
        l1 = l1 * a1 + s1;

        #pragma unroll
        for (int nt = 0; nt < 16; nt++) {
            o[nt][0] *= a0; o[nt][1] *= a0;
            o[nt][2] *= a1; o[nt][3] *= a1;
        }

        // ---- O += P'V' (3-term split) ----
        #pragma unroll
        for (int c = 0; c < 4; c++) {
            uint32_t pa0, pa1, pa2, pa3, la0, la1, la2, la3;
            split_pack(sacc[2*c][0],   sacc[2*c][1],   pa0, la0);
            split_pack(sacc[2*c][2],   sacc[2*c][3],   pa1, la1);
            split_pack(sacc[2*c+1][0], sacc[2*c+1][1], pa2, la2);
            split_pack(sacc[2*c+1][2], sacc[2*c+1][3], pa3, la3);
            #pragma unroll
            for (int dt = 0; dt < 8; dt++) {
                uint32_t vaddr = vs0 + ((c*16 + ((lane>>3)&1)*8 + (lane&7))*ALD
                                        + dt*16 + (lane>>4)*8)*2;
                uint32_t vh0,vh1,vh2,vh3, vl0,vl1,vl2,vl3;
                ldm4t(vh0,vh1,vh2,vh3, vaddr);
                ldm4t(vl0,vl1,vl2,vl3, vaddr + 128*2);
                mma_bf16(o[2*dt],   pa0,pa1,pa2,pa3, vh0,vh1);
                mma_bf16(o[2*dt],   pa0,pa1,pa2,pa3, vl0,vl1);
                mma_bf16(o[2*dt],   la0,la1,la2,la3, vh0,vh1);
                mma_bf16(o[2*dt+1], pa0,pa1,pa2,pa3, vh2,vh3);
                mma_bf16(o[2*dt+1], pa0,pa1,pa2,pa3, vl2,vl3);
                mma_bf16(o[2*dt+1], la0,la1,la2,la3, vh2,vh3);
            }
        }
        __syncthreads();
    }

    // ---- normalize + write ----
    const float rn0 = 1.f / l0, rn1 = 1.f / l1;
    const int b = bh >> 4, h = bh & 15;
    const int row0 = q0 + wq + lr;
    #pragma unroll
    for (int nt = 0; nt < 16; nt++) {
        int col = h*DH_ + nt*8 + 2*lc;
        *(float2*)(g_attn + (size_t)(b*S_ + row0)*C_ + col) =
            make_float2(o[nt][0]*rn0, o[nt][1]*rn0);
        *(float2*)(g_attn + (size_t)(b*S_ + row0 + 8)*C_ + col) =
            make_float2(o[nt][2]*rn1, o[nt][3]*rn1);
    }
}

// ---------------------------------------------------------------------------
extern "C" void kernel_launch(void* const* d_in, const int* in_sizes, int n_in,
                              void* d_out, int out_size) {
    const float* x     = (const float*)d_in[0];
    const float* Wqkv  = (const float*)d_in[1];
    const float* Wproj = (const float*)d_in[2];
    float* out = (float*)d_out;

    float *qkv_p, *attn_p;
    __nv_bfloat16 *a2_p, *b2_p;
    cudaGetSymbolAddress((void**)&qkv_p,  g_qkv);
    cudaGetSymbolAddress((void**)&attn_p, g_attn);
    cudaGetSymbolAddress((void**)&a2_p,   g_A2);
    cudaGetSymbolAddress((void**)&b2_p,   g_B2);

    cudaFuncSetAttribute(attn_mma_kernel,
                         cudaFuncAttributeMaxDynamicSharedMemorySize, ATT_SMEM);

    // 1) RoPE sin/cos table
    rope_table_kernel<<<(S_*64 + 255)/256, 256>>>();

    // 2) split-bf16 conversions for GEMM1
    conv_A_kernel<<<(B_*S_*C_)/256, 256>>>(x, C_);
    conv_B_kernel<<<dim3((3*C_)/32, C_/32), dim3(32, 8)>>>(Wqkv, C_, 3*C_);

    // 3) qkv = x @ Wqkv
    gemm_bf16_split<<<dim3((3*C_)/GBN, (B_*S_)/GBM), 256>>>(
        a2_p, b2_p, qkv_p, B_*S_, 3*C_);

    // 4) prep: RoPE + scale + split into per-head Q2/K2/V2
    prep_attn_kernel<<<(B_*S_*H_*64)/256, 256>>>();

    // 5) tensor-core causal flash attention -> g_attn
    attn_mma_kernel<<<dim3(S_/ABR, B_*H_), 256, ATT_SMEM>>>();

    // 6) split-bf16 conversions for GEMM2
    conv_A_kernel<<<(B_*S_*C_)/256, 256>>>(attn_p, C_);
    conv_B_kernel<<<dim3(C_/32, C_/32), dim3(32, 8)>>>(Wproj, C_, C_);

    // 7) out = attn @ Wproj
    gemm_bf16_split<<<dim3(C_/GBN, (B_*S_)/GBM), 256>>>(
        a2_p, b2_p, out, B_*S_, C_);
}

// round 5
// speedup vs baseline: 2.5199x; 1.0823x over previous
#include <cuda_runtime.h>
#include <cuda_bf16.h>
#include <math.h>
#include <stdint.h>

// Problem constants
#define B_   2
#define S_   2048
#define C_   2048
#define H_   16
#define DH_  128
#define RS_  (3*C_)
#define QSCALE 0.08838834764831845f

// Scratch (device globals)
__device__ float g_qkv[(size_t)B_*S_*3*C_];
__device__ __nv_bfloat16 g_A2[(size_t)B_*S_*2*C_];      // [4096][4096] = [hi|lo]
__device__ __nv_bfloat16 g_B2[(size_t)3*C_*2*C_];       // [6144][4096] = [hi|lo]
__device__ __nv_bfloat16 g_Q2[(size_t)B_*H_*S_*256];
__device__ __nv_bfloat16 g_K2[(size_t)B_*H_*S_*256];
__device__ __nv_bfloat16 g_V2[(size_t)B_*H_*S_*256];
__device__ float g_cos[S_*64];
__device__ float g_sin[S_*64];

#define AK2 (2*C_)        // 4096: row stride of A2/B2

__device__ __forceinline__ uint32_t smem_u32(const void* p) {
    uint32_t a;
    asm("{ .reg .u64 t; cvta.to.shared.u64 t, %1; cvt.u32.u64 %0, t; }" : "=r"(a) : "l"(p));
    return a;
}
__device__ __forceinline__ void cp16(uint32_t dst, const void* src) {
    asm volatile("cp.async.cg.shared.global [%0], [%1], 16;" :: "r"(dst), "l"(src));
}
__device__ __forceinline__ void ldm4(uint32_t& r0, uint32_t& r1, uint32_t& r2,
                                     uint32_t& r3, uint32_t addr) {
    asm volatile("ldmatrix.sync.aligned.m8n8.x4.shared.b16 {%0,%1,%2,%3}, [%4];"
        : "=r"(r0), "=r"(r1), "=r"(r2), "=r"(r3) : "r"(addr));
}
__device__ __forceinline__ void ldm4t(uint32_t& r0, uint32_t& r1, uint32_t& r2,
                                      uint32_t& r3, uint32_t addr) {
    asm volatile("ldmatrix.sync.aligned.m8n8.x4.trans.shared.b16 {%0,%1,%2,%3}, [%4];"
        : "=r"(r0), "=r"(r1), "=r"(r2), "=r"(r3) : "r"(addr));
}
__device__ __forceinline__ void mma_bf16(float* c, uint32_t a0, uint32_t a1,
                                         uint32_t a2, uint32_t a3,
                                         uint32_t b0, uint32_t b1) {
    asm volatile("mma.sync.aligned.m16n8k16.row.col.f32.bf16.bf16.f32 "
        "{%0,%1,%2,%3}, {%4,%5,%6,%7}, {%8,%9}, {%0,%1,%2,%3};"
        : "+f"(c[0]), "+f"(c[1]), "+f"(c[2]), "+f"(c[3])
        : "r"(a0), "r"(a1), "r"(a2), "r"(a3), "r"(b0), "r"(b1));
}
__device__ __forceinline__ void split_pack(float x, float y, uint32_t& hi, uint32_t& lo) {
    __nv_bfloat16 hx = __float2bfloat16(x);
    __nv_bfloat16 hy = __float2bfloat16(y);
    __nv_bfloat16 lx = __float2bfloat16(x - __bfloat162float(hx));
    __nv_bfloat16 ly = __float2bfloat16(y - __bfloat162float(hy));
    hi = (uint32_t)*(uint16_t*)&hx | ((uint32_t)*(uint16_t*)&hy << 16);
    lo = (uint32_t)*(uint16_t*)&lx | ((uint32_t)*(uint16_t*)&ly << 16);
}

// ---------------------------------------------------------------------------
// RoPE table
// ---------------------------------------------------------------------------
__global__ void rope_table_kernel() {
    int idx = blockIdx.x * blockDim.x + threadIdx.x;
    if (idx >= S_*64) return;
    int s = idx >> 6, d = idx & 63;
    float invf = (float)pow(10000.0, -(double)d / 64.0);
    float ang  = (float)s * invf;
    double a = (double)ang;
    g_cos[idx] = (float)cos(a);
    g_sin[idx] = (float)sin(a);
}

// ---------------------------------------------------------------------------
// Prep for attention: RoPE + scale + split-bf16, per-head layout [hi128|lo128]
// ---------------------------------------------------------------------------
__device__ __forceinline__ void split_st(__nv_bfloat16* dst, int off, float v) {
    __nv_bfloat16 hi = __float2bfloat16(v);
    dst[off]       = hi;
    dst[off + 128] = __float2bfloat16(v - __bfloat162float(hi));
}

__global__ void prep_attn_kernel() {
    int idx = blockIdx.x * blockDim.x + threadIdx.x;
    int d0 = idx & 63;
    int h  = (idx >> 6) & 15;
    int s  = (idx >> 10) & 2047;
    int b  = idx >> 21;
    size_t row = (size_t)(b*S_ + s) * RS_ + h*DH_;
    float c  = g_cos[s*64 + d0];
    float sn = g_sin[s*64 + d0];

    float k1 = g_qkv[row + d0],        k2 = g_qkv[row + d0 + 64];
    float q1 = g_qkv[row + C_ + d0],   q2 = g_qkv[row + C_ + d0 + 64];
    float v1 = g_qkv[row + 2*C_ + d0], v2 = g_qkv[row + 2*C_ + d0 + 64];

    float kr1 = k1*c - k2*sn, kr2 = k2*c + k1*sn;
    float qr1 = (q1*c - q2*sn) * QSCALE, qr2 = (q2*c + q1*sn) * QSCALE;

    size_t orow = ((size_t)(b*H_ + h) * S_ + s) * 256;
    split_st(g_Q2 + orow, d0, qr1);  split_st(g_Q2 + orow, d0 + 64, qr2);
    split_st(g_K2 + orow, d0, kr1);  split_st(g_K2 + orow, d0 + 64, kr2);
    split_st(g_V2 + orow, d0, v1);   split_st(g_V2 + orow, d0 + 64, v2);
}

// ---------------------------------------------------------------------------
// Split conversions: compact [hi|lo] layouts (stride AK2)
// ---------------------------------------------------------------------------
__global__ void conv_A_kernel(const float* __restrict__ A) {
    int idx = blockIdx.x * blockDim.x + threadIdx.x;   // M*2048
    int k = idx & (C_-1);
    int m = idx >> 11;
    float v = A[idx];
    __nv_bfloat16 hi = __float2bfloat16(v);
    __nv_bfloat16 lo = __float2bfloat16(v - __bfloat162float(hi));
    size_t base = (size_t)m * AK2;
    g_A2[base + k]       = hi;
    g_A2[base + C_ + k]  = lo;
}

// B2[n] = [hi(B^T)|lo(B^T)], B row-major [K=2048][N]
__global__ void conv_B_kernel(const float* __restrict__ W, int N) {
    __shared__ float tile[32][33];
    int n0 = blockIdx.x * 32, k0 = blockIdx.y * 32;
    int tx = threadIdx.x, ty = threadIdx.y;
    #pragma unroll
    for (int j = 0; j < 4; j++)
        tile[ty + 8*j][tx] = W[(size_t)(k0 + ty + 8*j) * N + n0 + tx];
    __syncthreads();
    #pragma unroll
    for (int j = 0; j < 4; j++) {
        int n = n0 + ty + 8*j;
        int k = k0 + tx;
        float v = tile[tx][ty + 8*j];
        __nv_bfloat16 hi = __float2bfloat16(v);
        __nv_bfloat16 lo = __float2bfloat16(v - __bfloat162float(hi));
        size_t base = (size_t)n * AK2;
        g_B2[base + k]      = hi;
        g_B2[base + C_ + k] = lo;
    }
}

// ---------------------------------------------------------------------------
// mma.sync bf16 GEMM, 3-term split via K-offset remap, 3-stage cp.async.
// Virtual K = 6144: A sections [hi,hi,lo], B sections [hi,lo,hi].
// ---------------------------------------------------------------------------
#define GBM 128
#define GBN 128
#define GBK 32
#define LDT 40
#define TILE_ELEMS (128*LDT)
#define NSTG 3
#define GEMM_NT 192                       // 6144/32
#define GEMM_SMEM (NSTG*2*TILE_ELEMS*2)   // 61440 B

__global__ void __launch_bounds__(256, 2) gemm_bf16_split(
    const __nv_bfloat16* __restrict__ A, const __nv_bfloat16* __restrict__ Bt,
    float* __restrict__ C, int M, int N)
{
    extern __shared__ __nv_bfloat16 gsm[];
    __nv_bfloat16* As = gsm;                       // [NSTG][TILE_ELEMS]
    __nv_bfloat16* Bs = gsm + NSTG*TILE_ELEMS;

    const int tid  = threadIdx.x;
    const int lane = tid & 31, wid = tid >> 5;
    const int wm = wid >> 2, wn = wid & 3;
    const int bm = blockIdx.y * GBM, bn = blockIdx.x * GBN;

    const uint32_t aBase = smem_u32(As);
    const uint32_t bBase = smem_u32(Bs);

    const int rg = tid >> 2, cg = (tid & 3) * 8;   // 16B-chunk coords (2/thread)

    const uint32_t aRowSel = (lane & 15), aColSel = (lane >> 4) * 8;
    const uint32_t bRowSel = ((lane >> 4) * 8) + (lane & 7);
    const uint32_t bColSel = ((lane >> 3) & 1) * 8;

    float acc[4][4][4];
    #pragma unroll
    for (int i = 0; i < 4; i++)
        #pragma unroll
        for (int j = 0; j < 4; j++)
            #pragma unroll
            for (int r = 0; r < 4; r++) acc[i][j][r] = 0.f;

    // stage loader: virtual chunk kt -> section-mapped K offsets
    auto load_stage = [&](int stg, int kt) {
        const int kv = kt * GBK;
        const int koffA = (kv < 2*C_) ? (kv & (C_-1)) : (kv - C_);
        const int koffB = (kv < 2*C_) ? kv : (kv - 2*C_);
        const uint32_t aD = aBase + stg * TILE_ELEMS * 2;
        const uint32_t bD = bBase + stg * TILE_ELEMS * 2;
        cp16(aD + (rg*LDT + cg)*2,        A  + (size_t)(bm + rg)*AK2      + koffA + cg);
        cp16(aD + ((rg+64)*LDT + cg)*2,   A  + (size_t)(bm + rg + 64)*AK2 + koffA + cg);
        cp16(bD + (rg*LDT + cg)*2,        Bt + (size_t)(bn + rg)*AK2      + koffB + cg);
        cp16(bD + ((rg+64)*LDT + cg)*2,   Bt + (size_t)(bn + rg + 64)*AK2 + koffB + cg);
        asm volatile("cp.async.commit_group;");
    };

    load_stage(0, 0);
    load_stage(1, 1);

    for (int kt = 0; kt < GEMM_NT; kt++) {
        if (kt < GEMM_NT - 1) asm volatile("cp.async.wait_group 1;");
        else                  asm volatile("cp.async.wait_group 0;");
        __syncthreads();

        if (kt + 2 < GEMM_NT) load_stage((kt + 2) % NSTG, kt + 2);

        const uint32_t aS = aBase + (kt % NSTG) * TILE_ELEMS * 2;
        const uint32_t bS = bBase + (kt % NSTG) * TILE_ELEMS * 2;

        #pragma unroll
        for (int kc = 0; kc < 2; kc++) {
            uint32_t bf[4][2];
            #pragma unroll
            for (int np = 0; np < 2; np++) {
                uint32_t addr = bS + ((wn*32 + np*16 + bRowSel) * LDT
                                      + kc*16 + bColSel) * 2;
                uint32_t r0, r1, r2, r3;
                ldm4(r0, r1, r2, r3, addr);
                bf[np*2+0][0] = r0; bf[np*2+0][1] = r1;
                bf[np*2+1][0] = r2; bf[np*2+1][1] = r3;
            }
            #pragma unroll
            for (int mt = 0; mt < 4; mt++) {
                uint32_t addr = aS + ((wm*64 + mt*16 + aRowSel) * LDT
                                      + kc*16 + aColSel) * 2;
                uint32_t a0, a1, a2, a3;
                ldm4(a0, a1, a2, a3, addr);
                #pragma unroll
                for (int nt = 0; nt < 4; nt++)
                    mma_bf16(acc[mt][nt], a0, a1, a2, a3, bf[nt][0], bf[nt][1]);
            }
        }
    }

    #pragma unroll
    for (int mt = 0; mt < 4; mt++) {
        const int r0 = bm + wm*64 + mt*16 + (lane >> 2);
        #pragma unroll
        for (int nt = 0; nt < 4; nt++) {
            const int col = bn + wn*32 + nt*8 + (lane & 3)*2;
            *(float2*)(C + (size_t)r0 * N + col) =
                make_float2(acc[mt][nt][0], acc[mt][nt][1]);
            *(float2*)(C + (size_t)(r0 + 8) * N + col) =
                make_float2(acc[mt][nt][2], acc[mt][nt][3]);
        }
    }
}

// ---------------------------------------------------------------------------
// Tensor-core flash attention; epilogue writes split-bf16 A2 directly.
// ---------------------------------------------------------------------------
#define ABR 128
#define ABC 64
#define ALD 264
#define QS_ELEMS (ABR*ALD)
#define KV_ELEMS (ABC*ALD)
#define ATT_SMEM ((QS_ELEMS + 4*KV_ELEMS)*2)

__global__ void __launch_bounds__(256, 1) attn_mma_kernel() {
    extern __shared__ __nv_bfloat16 attsm[];
    __nv_bfloat16* Qs = attsm;
    __nv_bfloat16* Ks = attsm + QS_ELEMS;
    __nv_bfloat16* Vs = attsm + QS_ELEMS + 2*KV_ELEMS;

    const int tid = threadIdx.x, lane = tid & 31, wid = tid >> 5;
    const int qt = gridDim.x - 1 - blockIdx.x;
    const int bh = blockIdx.y;
    const int q0 = qt * ABR;
    const size_t gbase = (size_t)bh * S_ * 256;

    const uint32_t qsB = smem_u32(Qs), ksB = smem_u32(Ks), vsB = smem_u32(Vs);

    {
        const __nv_bfloat16* qsrc = g_Q2 + gbase + (size_t)q0 * 256;
        #pragma unroll
        for (int i = 0; i < 16; i++) {
            int ch = tid + i*256;
            int r = ch >> 5, c8 = (ch & 31) * 8;
            cp16(qsB + (r*ALD + c8)*2, qsrc + (size_t)r*256 + c8);
        }
        const __nv_bfloat16* ksrc = g_K2 + gbase;
        const __nv_bfloat16* vsrc = g_V2 + gbase;
        #pragma unroll
        for (int i = 0; i < 8; i++) {
            int ch = tid + i*256;
            int r = ch >> 5, c8 = (ch & 31) * 8;
            cp16(ksB + (r*ALD + c8)*2, ksrc + (size_t)r*256 + c8);
            cp16(vsB + (r*ALD + c8)*2, vsrc + (size_t)r*256 + c8);
        }
        asm volatile("cp.async.commit_group;");
    }

    const int lr = lane >> 2, lc = lane & 3;
    const int wq = wid * 16;

    float m0 = -1e30f, m1 = -1e30f, l0 = 0.f, l1 = 0.f;
    float o[16][4];
    #pragma unroll
    for (int i = 0; i < 16; i++)
        #pragma unroll
        for (int j = 0; j < 4; j++) o[i][j] = 0.f;

    const int nkb = 2*qt + 2;

    for (int kb = 0; kb < nkb; kb++) {
        const int s = kb & 1;
        if (kb + 1 < nkb) {
            const int ns = s ^ 1;
            const __nv_bfloat16* ksrc = g_K2 + gbase + (size_t)((kb+1)*ABC) * 256;
            const __nv_bfloat16* vsrc = g_V2 + gbase + (size_t)((kb+1)*ABC) * 256;
            uint32_t kd = ksB + ns*KV_ELEMS*2, vd = vsB + ns*KV_ELEMS*2;
            #pragma unroll
            for (int i = 0; i < 8; i++) {
                int ch = tid + i*256;
                int r = ch >> 5, c8 = (ch & 31) * 8;
                cp16(kd + (r*ALD + c8)*2, ksrc + (size_t)r*256 + c8);
                cp16(vd + (r*ALD + c8)*2, vsrc + (size_t)r*256 + c8);
            }
            asm volatile("cp.async.commit_group;");
            asm volatile("cp.async.wait_group 1;");
        } else {
            asm volatile("cp.async.wait_group 0;");
        }
        __syncthreads();

        const uint32_t ks0 = ksB + s*KV_ELEMS*2;
        const uint32_t vs0 = vsB + s*KV_ELEMS*2;

        float sacc[8][4];
        #pragma unroll
        for (int i = 0; i < 8; i++)
            #pragma unroll
            for (int j = 0; j < 4; j++) sacc[i][j] = 0.f;

        #pragma unroll
        for (int kc = 0; kc < 8; kc++) {
            uint32_t qaddr = qsB + ((wq + (lane & 15))*ALD + kc*16 + (lane >> 4)*8)*2;
            uint32_t qh0,qh1,qh2,qh3, ql0,ql1,ql2,ql3;
            ldm4(qh0,qh1,qh2,qh3, qaddr);
            ldm4(ql0,ql1,ql2,ql3, qaddr + 128*2);
            #pragma unroll
            for (int ntp = 0; ntp < 4; ntp++) {
                uint32_t baddr = ks0 + ((ntp*16 + (lane>>4)*8 + (lane&7))*ALD
                                        + kc*16 + ((lane>>3)&1)*8)*2;
                uint32_t h0,h1,h2,h3, e0,e1,e2,e3;
                ldm4(h0,h1,h2,h3, baddr);
                ldm4(e0,e1,e2,e3, baddr + 128*2);
                mma_bf16(sacc[2*ntp],   qh0,qh1,qh2,qh3, h0,h1);
                mma_bf16(sacc[2*ntp],   qh0,qh1,qh2,qh3, e0,e1);
                mma_bf16(sacc[2*ntp],   ql0,ql1,ql2,ql3, h0,h1);
                mma_bf16(sacc[2*ntp+1], qh0,qh1,qh2,qh3, h2,h3);
                mma_bf16(sacc[2*ntp+1], qh0,qh1,qh2,qh3, e2,e3);
                mma_bf16(sacc[2*ntp+1], ql0,ql1,ql2,ql3, h2,h3);
            }
        }

        const int r0 = q0 + wq + lr, r1 = r0 + 8;
        if (kb >= 2*qt) {
            #pragma unroll
            for (int nt = 0; nt < 8; nt++) {
                int key = kb*ABC + nt*8 + 2*lc;
                if (key     > r0) sacc[nt][0] = -1e30f;
                if (key + 1 > r0) sacc[nt][1] = -1e30f;
                if (key     > r1) sacc[nt][2] = -1e30f;
                if (key + 1 > r1) sacc[nt][3] = -1e30f;
            }
        }

        float mx0 = m0, mx1 = m1;
        #pragma unroll
        for (int nt = 0; nt < 8; nt++) {
            mx0 = fmaxf(mx0, fmaxf(sacc[nt][0], sacc[nt][1]));
            mx1 = fmaxf(mx1, fmaxf(sacc[nt][2], sacc[nt][3]));
        }
        mx0 = fmaxf(mx0, __shfl_xor_sync(0xffffffffu, mx0, 1));
        mx0 = fmaxf(mx0, __shfl_xor_sync(0xffffffffu, mx0, 2));
        mx1 = fmaxf(mx1, __shfl_xor_sync(0xffffffffu, mx1, 1));
        mx1 = fmaxf(mx1, __shfl_xor_sync(0xffffffffu, mx1, 2));
        float a0 = __expf(m0 - mx0), a1 = __expf(m1 - mx1);
        m0 = mx0; m1 = mx1;

        float s0 = 0.f, s1 = 0.f;
        #pragma unroll
        for (int nt = 0; nt < 8; nt++) {
            sacc[nt][0] = __expf(sacc[nt][0] - m0); s0 += sacc[nt][0];
            sacc[nt][1] = __expf(sacc[nt][1] - m0); s0 += sacc[nt][1];
            sacc[nt][2] = __expf(sacc[nt][2] - m1); s1 += sacc[nt][2];
            sacc[nt][3] = __expf(sacc[nt][3] - m1); s1 += sacc[nt][3];
        }
        s0 += __shfl_xor_sync(0xffffffffu, s0, 1);
        s0 += __shfl_xor_sync(0xffffffffu, s0, 2);
        s1 += __shfl_xor_sync(0xffffffffu, s1, 1);
        s1 += __shfl_xor_sync(0xffffffffu, s1, 2);
        l0 = l0 * a0 + s0;
        l1 = l1 * a1 + s1;

        #pragma unroll
        for (int nt = 0; nt < 16; nt++) {
            o[nt][0] *= a0; o[nt][1] *= a0;
            o[nt][2] *= a1; o[nt][3] *= a1;
        }

        #pragma unroll
        for (int c = 0; c < 4; c++) {
            uint32_t pa0, pa1, pa2, pa3, la0, la1, la2, la3;
            split_pack(sacc[2*c][0],   sacc[2*c][1],   pa0, la0);
            split_pack(sacc[2*c][2],   sacc[2*c][3],   pa1, la1);
            split_pack(sacc[2*c+1][0], sacc[2*c+1][1], pa2, la2);
            split_pack(sacc[2*c+1][2], sacc[2*c+1][3], pa3, la3);
            #pragma unroll
            for (int dt = 0; dt < 8; dt++) {
                uint32_t vaddr = vs0 + ((c*16 + ((lane>>3)&1)*8 + (lane&7))*ALD
                                        + dt*16 + (lane>>4)*8)*2;
                uint32_t vh0,vh1,vh2,vh3, vl0,vl1,vl2,vl3;
                ldm4t(vh0,vh1,vh2,vh3, vaddr);
                ldm4t(vl0,vl1,vl2,vl3, vaddr + 128*2);
                mma_bf16(o[2*dt],   pa0,pa1,pa2,pa3, vh0,vh1);
                mma_bf16(o[2*dt],   pa0,pa1,pa2,pa3, vl0,vl1);
                mma_bf16(o[2*dt],   la0,la1,la2,la3, vh0,vh1);
                mma_bf16(o[2*dt+1], pa0,pa1,pa2,pa3, vh2,vh3);
                mma_bf16(o[2*dt+1], pa0,pa1,pa2,pa3, vl2,vl3);
                mma_bf16(o[2*dt+1], la0,la1,la2,la3, vh2,vh3);
            }
        }
        __syncthreads();
    }

    // ---- normalize + split-bf16 write directly into g_A2 [hi|lo] ----
    const float rn0 = 1.f / l0, rn1 = 1.f / l1;
    const int b = bh >> 4, h = bh & 15;
    const int row0 = q0 + wq + lr;
    const size_t rbase0 = (size_t)(b*S_ + row0) * AK2;
    const size_t rbase1 = (size_t)(b*S_ + row0 + 8) * AK2;
    #pragma unroll
    for (int nt = 0; nt < 16; nt++) {
        int col = h*DH_ + nt*8 + 2*lc;
        uint32_t h0, lo0, h1, lo1;
        split_pack(o[nt][0]*rn0, o[nt][1]*rn0, h0, lo0);
        split_pack(o[nt][2]*rn1, o[nt][3]*rn1, h1, lo1);
        *(uint32_t*)&g_A2[rbase0 + col]       = h0;
        *(uint32_t*)&g_A2[rbase0 + C_ + col]  = lo0;
        *(uint32_t*)&g_A2[rbase1 + col]       = h1;
        *(uint32_t*)&g_A2[rbase1 + C_ + col]  = lo1;
    }
}

// ---------------------------------------------------------------------------
extern "C" void kernel_launch(void* const* d_in, const int* in_sizes, int n_in,
                              void* d_out, int out_size) {
    const float* x     = (const float*)d_in[0];
    const float* Wqkv  = (const float*)d_in[1];
    const float* Wproj = (const float*)d_in[2];
    float* out = (float*)d_out;

    float* qkv_p;
    __nv_bfloat16 *a2_p, *b2_p;
    cudaGetSymbolAddress((void**)&qkv_p, g_qkv);
    cudaGetSymbolAddress((void**)&a2_p,  g_A2);
    cudaGetSymbolAddress((void**)&b2_p,  g_B2);

    cudaFuncSetAttribute(gemm_bf16_split,
                         cudaFuncAttributeMaxDynamicSharedMemorySize, GEMM_SMEM);
    cudaFuncSetAttribute(attn_mma_kernel,
                         cudaFuncAttributeMaxDynamicSharedMemorySize, ATT_SMEM);

    // 1) RoPE sin/cos table
    rope_table_kernel<<<(S_*64 + 255)/256, 256>>>();

    // 2) split conversions for GEMM1
    conv_A_kernel<<<(B_*S_*C_)/256, 256>>>(x);
    conv_B_kernel<<<dim3((3*C_)/32, C_/32), dim3(32, 8)>>>(Wqkv, 3*C_);

    // 3) qkv = x @ Wqkv
    gemm_bf16_split<<<dim3((3*C_)/GBN, (B_*S_)/GBM), 256, GEMM_SMEM>>>(
        a2_p, b2_p, qkv_p, B_*S_, 3*C_);

    // 4) prep: RoPE + scale + split into per-head Q2/K2/V2
    prep_attn_kernel<<<(B_*S_*H_*64)/256, 256>>>();

    // 5) tensor-core causal flash attention -> writes split A2 directly
    attn_mma_kernel<<<dim3(S_/ABR, B_*H_), 256, ATT_SMEM>>>();

    // 6) split conversion of Wproj only (attention already wrote A2)
    conv_B_kernel<<<dim3(C_/32, C_/32), dim3(32, 8)>>>(Wproj, C_);

    // 7) out = attn @ Wproj
    gemm_bf16_split<<<dim3(C_/GBN, (B_*S_)/GBM), 256, GEMM_SMEM>>>(
        a2_p, b2_p, out, B_*S_, C_);
}

// round 6
// speedup vs baseline: 2.5738x; 1.0214x over previous
#include <cuda_runtime.h>
#include <cuda_bf16.h>
#include <math.h>
#include <stdint.h>

// Problem constants
#define B_   2
#define S_   2048
#define C_   2048
#define H_   16
#define DH_  128
#define RS_  (3*C_)
#define QSCALE 0.08838834764831845f

// Scratch (device globals)
__device__ float g_qkv[(size_t)B_*S_*3*C_];
__device__ __nv_bfloat16 g_A2[(size_t)B_*S_*2*C_];      // [4096][4096] = [hi|lo]
__device__ __nv_bfloat16 g_B2[(size_t)3*C_*2*C_];       // [6144][4096] = [hi|lo]
__device__ __nv_bfloat16 g_Q2[(size_t)B_*H_*S_*256];
__device__ __nv_bfloat16 g_K2[(size_t)B_*H_*S_*256];
__device__ __nv_bfloat16 g_V2[(size_t)B_*H_*S_*256];
__device__ float g_cos[S_*64];
__device__ float g_sin[S_*64];

#define AK2 (2*C_)        // 4096: row stride of A2/B2

__device__ __forceinline__ uint32_t smem_u32(const void* p) {
    uint32_t a;
    asm("{ .reg .u64 t; cvta.to.shared.u64 t, %1; cvt.u32.u64 %0, t; }" : "=r"(a) : "l"(p));
    return a;
}
__device__ __forceinline__ void cp16(uint32_t dst, const void* src) {
    asm volatile("cp.async.cg.shared.global [%0], [%1], 16;" :: "r"(dst), "l"(src));
}
__device__ __forceinline__ void ldm4(uint32_t& r0, uint32_t& r1, uint32_t& r2,
                                     uint32_t& r3, uint32_t addr) {
    asm volatile("ldmatrix.sync.aligned.m8n8.x4.shared.b16 {%0,%1,%2,%3}, [%4];"
        : "=r"(r0), "=r"(r1), "=r"(r2), "=r"(r3) : "r"(addr));
}
__device__ __forceinline__ void ldm4t(uint32_t& r0, uint32_t& r1, uint32_t& r2,
                                      uint32_t& r3, uint32_t addr) {
    asm volatile("ldmatrix.sync.aligned.m8n8.x4.trans.shared.b16 {%0,%1,%2,%3}, [%4];"
        : "=r"(r0), "=r"(r1), "=r"(r2), "=r"(r3) : "r"(addr));
}
__device__ __forceinline__ void mma_bf16(float* c, uint32_t a0, uint32_t a1,
                                         uint32_t a2, uint32_t a3,
                                         uint32_t b0, uint32_t b1) {
    asm volatile("mma.sync.aligned.m16n8k16.row.col.f32.bf16.bf16.f32 "
        "{%0,%1,%2,%3}, {%4,%5,%6,%7}, {%8,%9}, {%0,%1,%2,%3};"
        : "+f"(c[0]), "+f"(c[1]), "+f"(c[2]), "+f"(c[3])
        : "r"(a0), "r"(a1), "r"(a2), "r"(a3), "r"(b0), "r"(b1));
}
__device__ __forceinline__ void split_pack(float x, float y, uint32_t& hi, uint32_t& lo) {
    __nv_bfloat16 hx = __float2bfloat16(x);
    __nv_bfloat16 hy = __float2bfloat16(y);
    __nv_bfloat16 lx = __float2bfloat16(x - __bfloat162float(hx));
    __nv_bfloat16 ly = __float2bfloat16(y - __bfloat162float(hy));
    hi = (uint32_t)*(uint16_t*)&hx | ((uint32_t)*(uint16_t*)&hy << 16);
    lo = (uint32_t)*(uint16_t*)&lx | ((uint32_t)*(uint16_t*)&ly << 16);
}

// ---------------------------------------------------------------------------
// RoPE table
// ---------------------------------------------------------------------------
__global__ void rope_table_kernel() {
    int idx = blockIdx.x * blockDim.x + threadIdx.x;
    if (idx >= S_*64) return;
    int s = idx >> 6, d = idx & 63;
    float invf = (float)pow(10000.0, -(double)d / 64.0);
    float ang  = (float)s * invf;
    double a = (double)ang;
    g_cos[idx] = (float)cos(a);
    g_sin[idx] = (float)sin(a);
}

// ---------------------------------------------------------------------------
// Prep for attention: RoPE + scale + split-bf16, per-head layout [hi128|lo128]
// ---------------------------------------------------------------------------
__device__ __forceinline__ void split_st(__nv_bfloat16* dst, int off, float v) {
    __nv_bfloat16 hi = __float2bfloat16(v);
    dst[off]       = hi;
    dst[off + 128] = __float2bfloat16(v - __bfloat162float(hi));
}

__global__ void prep_attn_kernel() {
    int idx = blockIdx.x * blockDim.x + threadIdx.x;
    int d0 = idx & 63;
    int h  = (idx >> 6) & 15;
    int s  = (idx >> 10) & 2047;
    int b  = idx >> 21;
    size_t row = (size_t)(b*S_ + s) * RS_ + h*DH_;
    float c  = g_cos[s*64 + d0];
    float sn = g_sin[s*64 + d0];

    float k1 = g_qkv[row + d0],        k2 = g_qkv[row + d0 + 64];
    float q1 = g_qkv[row + C_ + d0],   q2 = g_qkv[row + C_ + d0 + 64];
    float v1 = g_qkv[row + 2*C_ + d0], v2 = g_qkv[row + 2*C_ + d0 + 64];

    float kr1 = k1*c - k2*sn, kr2 = k2*c + k1*sn;
    float qr1 = (q1*c - q2*sn) * QSCALE, qr2 = (q2*c + q1*sn) * QSCALE;

    size_t orow = ((size_t)(b*H_ + h) * S_ + s) * 256;
    split_st(g_Q2 + orow, d0, qr1);  split_st(g_Q2 + orow, d0 + 64, qr2);
    split_st(g_K2 + orow, d0, kr1);  split_st(g_K2 + orow, d0 + 64, kr2);
    split_st(g_V2 + orow, d0, v1);   split_st(g_V2 + orow, d0 + 64, v2);
}

// ---------------------------------------------------------------------------
// Split conversions: compact [hi|lo] layouts (stride AK2)
// ---------------------------------------------------------------------------
__global__ void conv_A_kernel(const float* __restrict__ A) {
    int idx = blockIdx.x * blockDim.x + threadIdx.x;
    int k = idx & (C_-1);
    int m = idx >> 11;
    float v = A[idx];
    __nv_bfloat16 hi = __float2bfloat16(v);
    __nv_bfloat16 lo = __float2bfloat16(v - __bfloat162float(hi));
    size_t base = (size_t)m * AK2;
    g_A2[base + k]       = hi;
    g_A2[base + C_ + k]  = lo;
}

__global__ void conv_B_kernel(const float* __restrict__ W, int N) {
    __shared__ float tile[32][33];
    int n0 = blockIdx.x * 32, k0 = blockIdx.y * 32;
    int tx = threadIdx.x, ty = threadIdx.y;
    #pragma unroll
    for (int j = 0; j < 4; j++)
        tile[ty + 8*j][tx] = W[(size_t)(k0 + ty + 8*j) * N + n0 + tx];
    __syncthreads();
    #pragma unroll
    for (int j = 0; j < 4; j++) {
        int n = n0 + ty + 8*j;
        int k = k0 + tx;
        float v = tile[tx][ty + 8*j];
        __nv_bfloat16 hi = __float2bfloat16(v);
        __nv_bfloat16 lo = __float2bfloat16(v - __bfloat162float(hi));
        size_t base = (size_t)n * AK2;
        g_B2[base + k]      = hi;
        g_B2[base + C_ + k] = lo;
    }
}

// ---------------------------------------------------------------------------
// mma.sync bf16 GEMM: 128x128 CTA tile, 4 warps (64x64 each), GBK=64,
// 3-stage cp.async, 3-term split via K-offset remap (virtual K = 6144).
// ---------------------------------------------------------------------------
#define GBM 128
#define GBN 128
#define GBK 64
#define LDT 72                      // padded row stride (elems) = 144 B
#define OP_ELEMS (128*LDT)          // per operand per stage
#define NSTG 3
#define GEMM_NT 96                  // 6144/64
#define GEMM_SMEM (NSTG*2*OP_ELEMS*2)   // 110592 B

__global__ void __launch_bounds__(128, 2) gemm_bf16_split(
    const __nv_bfloat16* __restrict__ A, const __nv_bfloat16* __restrict__ Bt,
    float* __restrict__ C, int M, int N)
{
    extern __shared__ __nv_bfloat16 gsm[];
    __nv_bfloat16* As = gsm;                    // [NSTG][OP_ELEMS]
    __nv_bfloat16* Bs = gsm + NSTG*OP_ELEMS;

    const int tid  = threadIdx.x;
    const int lane = tid & 31, wid = tid >> 5;
    const int wm = wid >> 1, wn = wid & 1;      // 2 x 2 warp grid
    const int bm = blockIdx.y * GBM, bn = blockIdx.x * GBN;

    const uint32_t aBase = smem_u32(As);
    const uint32_t bBase = smem_u32(Bs);

    const uint32_t aRowSel = (lane & 15), aColSel = (lane >> 4) * 8;
    const uint32_t bRowSel = ((lane >> 4) * 8) + (lane & 7);
    const uint32_t bColSel = ((lane >> 3) & 1) * 8;

    float acc[4][8][4];
    #pragma unroll
    for (int i = 0; i < 4; i++)
        #pragma unroll
        for (int j = 0; j < 8; j++)
            #pragma unroll
            for (int r = 0; r < 4; r++) acc[i][j][r] = 0.f;

    // stage loader: row = chunk>>3, col8 = (chunk&7)*8; 8 chunks/thread/operand
    auto load_stage = [&](int stg, int kt) {
        const int kv = kt * GBK;
        const int koffA = (kv < 2*C_) ? (kv & (C_-1)) : (kv - C_);
        const int koffB = (kv < 2*C_) ? kv : (kv - 2*C_);
        const uint32_t aD = aBase + stg * OP_ELEMS * 2;
        const uint32_t bD = bBase + stg * OP_ELEMS * 2;
        #pragma unroll
        for (int i = 0; i < 8; i++) {
            int ch = tid + i * 128;
            int r = ch >> 3, c8 = (ch & 7) * 8;
            cp16(aD + (r*LDT + c8)*2, A  + (size_t)(bm + r)*AK2 + koffA + c8);
            cp16(bD + (r*LDT + c8)*2, Bt + (size_t)(bn + r)*AK2 + koffB + c8);
        }
        asm volatile("cp.async.commit_group;");
    };

    load_stage(0, 0);
    load_stage(1, 1);

    for (int kt = 0; kt < GEMM_NT; kt++) {
        if (kt < GEMM_NT - 1) asm volatile("cp.async.wait_group 1;");
        else                  asm volatile("cp.async.wait_group 0;");
        __syncthreads();

        if (kt + 2 < GEMM_NT) load_stage((kt + 2) % NSTG, kt + 2);

        const uint32_t aS = aBase + (kt % NSTG) * OP_ELEMS * 2;
        const uint32_t bS = bBase + (kt % NSTG) * OP_ELEMS * 2;

        #pragma unroll
        for (int kc = 0; kc < 4; kc++) {
            uint32_t bf[8][2];
            #pragma unroll
            for (int np = 0; np < 4; np++) {
                uint32_t addr = bS + ((wn*64 + np*16 + bRowSel) * LDT
                                      + kc*16 + bColSel) * 2;
                uint32_t r0, r1, r2, r3;
                ldm4(r0, r1, r2, r3, addr);
                bf[np*2+0][0] = r0; bf[np*2+0][1] = r1;
                bf[np*2+1][0] = r2; bf[np*2+1][1] = r3;
            }
            #pragma unroll
            for (int mt = 0; mt < 4; mt++) {
                uint32_t addr = aS + ((wm*64 + mt*16 + aRowSel) * LDT
                                      + kc*16 + aColSel) * 2;
                uint32_t a0, a1, a2, a3;
                ldm4(a0, a1, a2, a3, addr);
                #pragma unroll
                for (int nt = 0; nt < 8; nt++)
                    mma_bf16(acc[mt][nt], a0, a1, a2, a3, bf[nt][0], bf[nt][1]);
            }
        }
    }

    #pragma unroll
    for (int mt = 0; mt < 4; mt++) {
        const int r0 = bm + wm*64 + mt*16 + (lane >> 2);
        #pragma unroll
        for (int nt = 0; nt < 8; nt++) {
            const int col = bn + wn*64 + nt*8 + (lane & 3)*2;
            *(float2*)(C + (size_t)r0 * N + col) =
                make_float2(acc[mt][nt][0], acc[mt][nt][1]);
            *(float2*)(C + (size_t)(r0 + 8) * N + col) =
                make_float2(acc[mt][nt][2], acc[mt][nt][3]);
        }
    }
}

// ---------------------------------------------------------------------------
// Tensor-core flash attention; epilogue writes split-bf16 A2 directly.
// ---------------------------------------------------------------------------
#define ABR 128
#define ABC 64
#define ALD 264
#define QS_ELEMS (ABR*ALD)
#define KV_ELEMS (ABC*ALD)
#define ATT_SMEM ((QS_ELEMS + 4*KV_ELEMS)*2)

__global__ void __launch_bounds__(256, 1) attn_mma_kernel() {
    extern __shared__ __nv_bfloat16 attsm[];
    __nv_bfloat16* Qs = attsm;
    __nv_bfloat16* Ks = attsm + QS_ELEMS;
    __nv_bfloat16* Vs = attsm + QS_ELEMS + 2*KV_ELEMS;

    const int tid = threadIdx.x, lane = tid & 31, wid = tid >> 5;
    const int qt = gridDim.x - 1 - blockIdx.x;
    const int bh = blockIdx.y;
    const int q0 = qt * ABR;
    const size_t gbase = (size_t)bh * S_ * 256;

    const uint32_t qsB = smem_u32(Qs), ksB = smem_u32(Ks), vsB = smem_u32(Vs);

    {
        const __nv_bfloat16* qsrc = g_Q2 + gbase + (size_t)q0 * 256;
        #pragma unroll
        for (int i = 0; i < 16; i++) {
            int ch = tid + i*256;
            int r = ch >> 5, c8 = (ch & 31) * 8;
            cp16(qsB + (r*ALD + c8)*2, qsrc + (size_t)r*256 + c8);
        }
        const __nv_bfloat16* ksrc = g_K2 + gbase;
        const __nv_bfloat16* vsrc = g_V2 + gbase;
        #pragma unroll
        for (int i = 0; i < 8; i++) {
            int ch = tid + i*256;
            int r = ch >> 5, c8 = (ch & 31) * 8;
            cp16(ksB + (r*ALD + c8)*2, ksrc + (size_t)r*256 + c8);
            cp16(vsB + (r*ALD + c8)*2, vsrc + (size_t)r*256 + c8);
        }
        asm volatile("cp.async.commit_group;");
    }

    const int lr = lane >> 2, lc = lane & 3;
    const int wq = wid * 16;

    float m0 = -1e30f, m1 = -1e30f, l0 = 0.f, l1 = 0.f;
    float o[16][4];
    #pragma unroll
    for (int i = 0; i < 16; i++)
        #pragma unroll
        for (int j = 0; j < 4; j++) o[i][j] = 0.f;

    const int nkb = 2*qt + 2;

    for (int kb = 0; kb < nkb; kb++) {
        const int s = kb & 1;
        if (kb + 1 < nkb) {
            const int ns = s ^ 1;
            const __nv_bfloat16* ksrc = g_K2 + gbase + (size_t)((kb+1)*ABC) * 256;
            const __nv_bfloat16* vsrc = g_V2 + gbase + (size_t)((kb+1)*ABC) * 256;
            uint32_t kd = ksB + ns*KV_ELEMS*2, vd = vsB + ns*KV_ELEMS*2;
            #pragma unroll
            for (int i = 0; i < 8; i++) {
                int ch = tid + i*256;
                int r = ch >> 5, c8 = (ch & 31) * 8;
                cp16(kd + (r*ALD + c8)*2, ksrc + (size_t)r*256 + c8);
                cp16(vd + (r*ALD + c8)*2, vsrc + (size_t)r*256 + c8);
            }
            asm volatile("cp.async.commit_group;");
            asm volatile("cp.async.wait_group 1;");
        } else {
            asm volatile("cp.async.wait_group 0;");
        }
        __syncthreads();

        const uint32_t ks0 = ksB + s*KV_ELEMS*2;
        const uint32_t vs0 = vsB + s*KV_ELEMS*2;

        float sacc[8][4];
        #pragma unroll
        for (int i = 0; i < 8; i++)
            #pragma unroll
            for (int j = 0; j < 4; j++) sacc[i][j] = 0.f;

        #pragma unroll
        for (int kc = 0; kc < 8; kc++) {
            uint32_t qaddr = qsB + ((wq + (lane & 15))*ALD + kc*16 + (lane >> 4)*8)*2;
            uint32_t qh0,qh1,qh2,qh3, ql0,ql1,ql2,ql3;
            ldm4(qh0,qh1,qh2,qh3, qaddr);
            ldm4(ql0,ql1,ql2,ql3, qaddr + 128*2);
            #pragma unroll
            for (int ntp = 0; ntp < 4; ntp++) {
                uint32_t baddr = ks0 + ((ntp*16 + (lane>>4)*8 + (lane&7))*ALD
                                        + kc*16 + ((lane>>3)&1)*8)*2;
                uint32_t h0,h1,h2,h3, e0,e1,e2,e3;
                ldm4(h0,h1,h2,h3, baddr);
                ldm4(e0,e1,e2,e3, baddr + 128*2);
                mma_bf16(sacc[2*ntp],   qh0,qh1,qh2,qh3, h0,h1);
                mma_bf16(sacc[2*ntp],   qh0,qh1,qh2,qh3, e0,e1);
                mma_bf16(sacc[2*ntp],   ql0,ql1,ql2,ql3, h0,h1);
                mma_bf16(sacc[2*ntp+1], qh0,qh1,qh2,qh3, h2,h3);
                mma_bf16(sacc[2*ntp+1], qh0,qh1,qh2,qh3, e2,e3);
                mma_bf16(sacc[2*ntp+1], ql0,ql1,ql2,ql3, h2,h3);
            }
        }

        const int r0 = q0 + wq + lr, r1 = r0 + 8;
        if (kb >= 2*qt) {
            #pragma unroll
            for (int nt = 0; nt < 8; nt++) {
                int key = kb*ABC + nt*8 + 2*lc;
                if (key     > r0) sacc[nt][0] = -1e30f;
                if (key + 1 > r0) sacc[nt][1] = -1e30f;
                if (key     > r1) sacc[nt][2] = -1e30f;
                if (key + 1 > r1) sacc[nt][3] = -1e30f;
            }
        }

        float mx0 = m0, mx1 = m1;
        #pragma unroll
        for (int nt = 0; nt < 8; nt++) {
            mx0 = fmaxf(mx0, fmaxf(sacc[nt][0], sacc[nt][1]));
            mx1 = fmaxf(mx1, fmaxf(sacc[nt][2], sacc[nt][3]));
        }
        mx0 = fmaxf(mx0, __shfl_xor_sync(0xffffffffu, mx0, 1));
        mx0 = fmaxf(mx0, __shfl_xor_sync(0xffffffffu, mx0, 2));
        mx1 = fmaxf(mx1, __shfl_xor_sync(0xffffffffu, mx1, 1));
        mx1 = fmaxf(mx1, __shfl_xor_sync(0xffffffffu, mx1, 2));
        float a0 = __expf(m0 - mx0), a1 = __expf(m1 - mx1);
        m0 = mx0; m1 = mx1;

        float s0 = 0.f, s1 = 0.f;
        #pragma unroll
        for (int nt = 0; nt < 8; nt++) {
            sacc[nt][0] = __expf(sacc[nt][0] - m0); s0 += sacc[nt][0];
            sacc[nt][1] = __expf(sacc[nt][1] - m0); s0 += sacc[nt][1];
            sacc[nt][2] = __expf(sacc[nt][2] - m1); s1 += sacc[nt][2];
            sacc[nt][3] = __expf(sacc[nt][3] - m1); s1 += sacc[nt][3];
        }
        s0 += __shfl_xor_sync(0xffffffffu, s0, 1);
        s0 += __shfl_xor_sync(0xffffffffu, s0, 2);
        s1 += __shfl_xor_sync(0xffffffffu, s1, 1);
        s1 += __shfl_xor_sync(0xffffffffu, s1, 2);
        l0 = l0 * a0 + s0;
        l1 = l1 * a1 + s1;

        #pragma unroll
        for (int nt = 0; nt < 16; nt++) {
            o[nt][0] *= a0; o[nt][1] *= a0;
            o[nt][2] *= a1; o[nt][3] *= a1;
        }

        #pragma unroll
        for (int c = 0; c < 4; c++) {
            uint32_t pa0, pa1, pa2, pa3, la0, la1, la2, la3;
            split_pack(sacc[2*c][0],   sacc[2*c][1],   pa0, la0);
            split_pack(sacc[2*c][2],   sacc[2*c][3],   pa1, la1);
            split_pack(sacc[2*c+1][0], sacc[2*c+1][1], pa2, la2);
            split_pack(sacc[2*c+1][2], sacc[2*c+1][3], pa3, la3);
            #pragma unroll
            for (int dt = 0; dt < 8; dt++) {
                uint32_t vaddr = vs0 + ((c*16 + ((lane>>3)&1)*8 + (lane&7))*ALD
                                        + dt*16 + (lane>>4)*8)*2;
                uint32_t vh0,vh1,vh2,vh3, vl0,vl1,vl2,vl3;
                ldm4t(vh0,vh1,vh2,vh3, vaddr);
                ldm4t(vl0,vl1,vl2,vl3, vaddr + 128*2);
                mma_bf16(o[2*dt],   pa0,pa1,pa2,pa3, vh0,vh1);
                mma_bf16(o[2*dt],   pa0,pa1,pa2,pa3, vl0,vl1);
                mma_bf16(o[2*dt],   la0,la1,la2,la3, vh0,vh1);
                mma_bf16(o[2*dt+1], pa0,pa1,pa2,pa3, vh2,vh3);
                mma_bf16(o[2*dt+1], pa0,pa1,pa2,pa3, vl2,vl3);
                mma_bf16(o[2*dt+1], la0,la1,la2,la3, vh2,vh3);
            }
        }
        __syncthreads();
    }

    const float rn0 = 1.f / l0, rn1 = 1.f / l1;
    const int b = bh >> 4, h = bh & 15;
    const int row0 = q0 + wq + lr;
    const size_t rbase0 = (size_t)(b*S_ + row0) * AK2;
    const size_t rbase1 = (size_t)(b*S_ + row0 + 8) * AK2;
    #pragma unroll
    for (int nt = 0; nt < 16; nt++) {
        int col = h*DH_ + nt*8 + 2*lc;
        uint32_t h0, lo0, h1, lo1;
        split_pack(o[nt][0]*rn0, o[nt][1]*rn0, h0, lo0);
        split_pack(o[nt][2]*rn1, o[nt][3]*rn1, h1, lo1);
        *(uint32_t*)&g_A2[rbase0 + col]       = h0;
        *(uint32_t*)&g_A2[rbase0 + C_ + col]  = lo0;
        *(uint32_t*)&g_A2[rbase1 + col]       = h1;
        *(uint32_t*)&g_A2[rbase1 + C_ + col]  = lo1;
    }
}

// ---------------------------------------------------------------------------
extern "C" void kernel_launch(void* const* d_in, const int* in_sizes, int n_in,
                              void* d_out, int out_size) {
    const float* x     = (const float*)d_in[0];
    const float* Wqkv  = (const float*)d_in[1];
    const float* Wproj = (const float*)d_in[2];
    float* out = (float*)d_out;

    float* qkv_p;
    __nv_bfloat16 *a2_p, *b2_p;
    cudaGetSymbolAddress((void**)&qkv_p, g_qkv);
    cudaGetSymbolAddress((void**)&a2_p,  g_A2);
    cudaGetSymbolAddress((void**)&b2_p,  g_B2);

    cudaFuncSetAttribute(gemm_bf16_split,
                         cudaFuncAttributeMaxDynamicSharedMemorySize, GEMM_SMEM);
    cudaFuncSetAttribute(attn_mma_kernel,
                         cudaFuncAttributeMaxDynamicSharedMemorySize, ATT_SMEM);

    // 1) RoPE sin/cos table
    rope_table_kernel<<<(S_*64 + 255)/256, 256>>>();

    // 2) split conversions for GEMM1
    conv_A_kernel<<<(B_*S_*C_)/256, 256>>>(x);
    conv_B_kernel<<<dim3((3*C_)/32, C_/32), dim3(32, 8)>>>(Wqkv, 3*C_);

    // 3) qkv = x @ Wqkv
    gemm_bf16_split<<<dim3((3*C_)/GBN, (B_*S_)/GBM), 128, GEMM_SMEM>>>(
        a2_p, b2_p, qkv_p, B_*S_, 3*C_);

    // 4) prep: RoPE + scale + split into per-head Q2/K2/V2
    prep_attn_kernel<<<(B_*S_*H_*64)/256, 256>>>();

    // 5) tensor-core causal flash attention -> writes split A2 directly
    attn_mma_kernel<<<dim3(S_/ABR, B_*H_), 256, ATT_SMEM>>>();

    // 6) split conversion of Wproj only
    conv_B_kernel<<<dim3(C_/32, C_/32), dim3(32, 8)>>>(Wproj, C_);

    // 7) out = attn @ Wproj
    gemm_bf16_split<<<dim3(C_/GBN, (B_*S_)/GBM), 128, GEMM_SMEM>>>(
        a2_p, b2_p, out, B_*S_, C_);
}